// round 7
// baseline (speedup 1.0000x reference)
#include <cuda_runtime.h>
#include <mma.h>
#include <math.h>
#include <stdint.h>

using namespace nvcuda;

// Shapes: B=8, L=64, S=2048, D=1024, C=1024, H=16, HD=64

// ---------------- device scratch ----------------
__device__ float g_fuse6[6 * 1024 * 1024];   // rounded fusion inputs
__device__ float g_ctx_r[16384 * 1024];      // rounded context
__device__ float g_lat_r[512 * 1024];        // rounded latents
__device__ float g_outw_r[1024 * 1024];
__device__ float g_ffw1_r[4096 * 1024];
__device__ float g_ffw2_r[1024 * 4096];
__device__ float g_Wq[1024 * 1024];          // fused+rounded q weight
__device__ float g_Wkv[2048 * 1024];         // fused+rounded k|v weights
__device__ float g_bq[1024];
__device__ float g_bkv[2048];
__device__ float g_qh[512 * 1024];           // q heads (rounded); reused for attn_out
__device__ float g_kv[16384 * 2048];         // kh | vh interleaved per row (rounded)
__device__ float g_probs[8192 * 2048];       // [B,H,L,S] (rounded post-softmax)
__device__ float g_part[4 * 512 * 1024];     // attn split-K partials
__device__ float g_attn[512 * 1024];         // attn concat (rounded); reused for ff2 out
__device__ float g_x[512 * 1024];            // post-LN1 exact
__device__ float g_xr[512 * 1024];           // post-LN1 rounded
__device__ float g_h1[512 * 4096];           // ff hidden (rounded)

__device__ __forceinline__ float gelu_exact(float x) {
    return 0.5f * x * (1.0f + erff(x * 0.70710678118654752f));
}
__device__ __forceinline__ float rtf(float x) {
    float y;
    asm("cvt.rna.tf32.f32 %0, %1;" : "=f"(y) : "f"(x));
    return y;
}
__device__ __forceinline__ void cp16(uint32_t dst, const void* src) {
    asm volatile("cp.async.cg.shared.global [%0], [%1], 16;\n" ::"r"(dst), "l"(src));
}
#define CP_COMMIT() asm volatile("cp.async.commit_group;\n" ::)
#define CP_WAIT(n) asm volatile("cp.async.wait_group %0;\n" ::"n"(n))

// ---------------- rounding kernels ----------------
__global__ void round_tf32_kernel(const float4* __restrict__ in, float4* __restrict__ out, int n4) {
    int i = blockIdx.x * 256 + threadIdx.x;
    if (i < n4) {
        float4 v = in[i];
        v.x = rtf(v.x); v.y = rtf(v.y); v.z = rtf(v.z); v.w = rtf(v.w);
        out[i] = v;
    }
}
__global__ void round6_kernel(const float4* a0, const float4* a1, const float4* a2,
                              const float4* a3, const float4* a4, const float4* a5,
                              float4* __restrict__ out) {
    const float4* srcs[6] = {a0, a1, a2, a3, a4, a5};
    int z = blockIdx.y;
    int i = blockIdx.x * 256 + threadIdx.x;
    float4 v = srcs[z][i];
    v.x = rtf(v.x); v.y = rtf(v.y); v.z = rtf(v.z); v.w = rtf(v.w);
    out[(size_t)z * 262144 + i] = v;
}

// ---------------- bias fusion ----------------
__global__ void fuse_bias_kernel(const float* __restrict__ W, const float* __restrict__ bin,
                                 const float* __restrict__ badd, float* __restrict__ bout) {
    int o = blockIdx.x;
    float s = 0.f;
    for (int i = threadIdx.x; i < 1024; i += 256) s += W[o * 1024 + i] * bin[i];
    __shared__ float red[256];
    red[threadIdx.x] = s;
    __syncthreads();
    for (int st = 128; st > 0; st >>= 1) {
        if (threadIdx.x < st) red[threadIdx.x] += red[threadIdx.x + st];
        __syncthreads();
    }
    if (threadIdx.x == 0) bout[o] = red[0] + badd[o];
}

// ==================== TF32 WMMA GEMM 128x128 (generic) ====================
template <int NT, int EPI, int BIAS, int RND>
__device__ __forceinline__ void gemm_body(const float* __restrict__ A, const float* __restrict__ B,
                                          const float* __restrict__ bias, float* __restrict__ C,
                                          int M, int N, int K, float* sm) {
    int tid = threadIdx.x;
    int wid = tid >> 5, lane = tid & 31;
    int warpRow = wid >> 2, warpCol = wid & 3;
    int bm = blockIdx.y * 128, bn = blockIdx.x * 128;

    uint32_t s_base = (uint32_t)__cvta_generic_to_shared(sm);
    int ra = tid >> 3, ca = (tid & 7) * 4;
    int kb = tid >> 5, cb = (tid & 31) * 4;

    wmma::fragment<wmma::accumulator, 16, 16, 8, float> acc[4][2];
#pragma unroll
    for (int i = 0; i < 4; ++i)
#pragma unroll
        for (int j = 0; j < 2; ++j) wmma::fill_fragment(acc[i][j], 0.0f);

    const int KT = K >> 5;
    auto issue = [&](int stage, int k0) {
        uint32_t as = s_base + (uint32_t)(stage * 5120) * 4;
        uint32_t bs = s_base + (uint32_t)(10240 + stage * 5120) * 4;
#pragma unroll
        for (int it = 0; it < 4; ++it) {
            int r = ra + it * 32;
            cp16(as + (uint32_t)(r * 40 + ca) * 4, A + (size_t)(bm + r) * K + k0 + ca);
        }
        if (NT) {
#pragma unroll
            for (int it = 0; it < 4; ++it) {
                int r = ra + it * 32;
                cp16(bs + (uint32_t)(r * 40 + ca) * 4, B + (size_t)(bn + r) * K + k0 + ca);
            }
        } else {
#pragma unroll
            for (int it = 0; it < 4; ++it) {
                int kk = kb + it * 8;
                cp16(bs + (uint32_t)(kk * 136 + cb) * 4, B + (size_t)(k0 + kk) * N + bn + cb);
            }
        }
        CP_COMMIT();
    };

    issue(0, 0);
    for (int kt = 0; kt < KT; ++kt) {
        int stage = kt & 1;
        if (kt + 1 < KT) {
            issue(stage ^ 1, (kt + 1) * 32);
            CP_WAIT(1);
        } else {
            CP_WAIT(0);
        }
        __syncthreads();
        float* As = sm + stage * 5120;
        float* Bs = sm + 10240 + stage * 5120;
#pragma unroll
        for (int ks = 0; ks < 4; ++ks) {
            int kk = ks * 8;
            wmma::fragment<wmma::matrix_a, 16, 16, 8, wmma::precision::tf32, wmma::row_major> af[4];
#pragma unroll
            for (int i = 0; i < 4; ++i)
                wmma::load_matrix_sync(af[i], &As[(warpRow * 64 + i * 16) * 40 + kk], 40);
            if (NT) {
                wmma::fragment<wmma::matrix_b, 16, 16, 8, wmma::precision::tf32, wmma::col_major> bf[2];
#pragma unroll
                for (int j = 0; j < 2; ++j)
                    wmma::load_matrix_sync(bf[j], &Bs[(warpCol * 32 + j * 16) * 40 + kk], 40);
#pragma unroll
                for (int i = 0; i < 4; ++i)
#pragma unroll
                    for (int j = 0; j < 2; ++j) wmma::mma_sync(acc[i][j], af[i], bf[j], acc[i][j]);
            } else {
                wmma::fragment<wmma::matrix_b, 16, 16, 8, wmma::precision::tf32, wmma::row_major> bf[2];
#pragma unroll
                for (int j = 0; j < 2; ++j)
                    wmma::load_matrix_sync(bf[j], &Bs[kk * 136 + warpCol * 32 + j * 16], 136);
#pragma unroll
                for (int i = 0; i < 4; ++i)
#pragma unroll
                    for (int j = 0; j < 2; ++j) wmma::mma_sync(acc[i][j], af[i], bf[j], acc[i][j]);
            }
        }
        __syncthreads();
    }

    float* st = &sm[wid * 384];
#pragma unroll
    for (int i = 0; i < 4; ++i) {
#pragma unroll
        for (int j = 0; j < 2; ++j) {
            wmma::store_matrix_sync(st, acc[i][j], 24, wmma::mem_row_major);
            __syncwarp();
            int row0 = bm + warpRow * 64 + i * 16;
            int col0 = bn + warpCol * 32 + j * 16;
            int r = lane >> 1, c8 = (lane & 1) * 8;
            float4 v0 = *(float4*)&st[r * 24 + c8];
            float4 v1 = *(float4*)&st[r * 24 + c8 + 4];
            if (BIAS) {
                const float* bp = bias + col0 + c8;
                v0.x += bp[0]; v0.y += bp[1]; v0.z += bp[2]; v0.w += bp[3];
                v1.x += bp[4]; v1.y += bp[5]; v1.z += bp[6]; v1.w += bp[7];
            }
            if (EPI) {
                v0.x = gelu_exact(v0.x); v0.y = gelu_exact(v0.y);
                v0.z = gelu_exact(v0.z); v0.w = gelu_exact(v0.w);
                v1.x = gelu_exact(v1.x); v1.y = gelu_exact(v1.y);
                v1.z = gelu_exact(v1.z); v1.w = gelu_exact(v1.w);
            }
            if (RND) {
                v0.x = rtf(v0.x); v0.y = rtf(v0.y); v0.z = rtf(v0.z); v0.w = rtf(v0.w);
                v1.x = rtf(v1.x); v1.y = rtf(v1.y); v1.z = rtf(v1.z); v1.w = rtf(v1.w);
            }
            float* cp = C + (size_t)(row0 + r) * N + col0 + c8;
            *(float4*)cp = v0;
            *(float4*)(cp + 4) = v1;
            __syncwarp();
        }
    }
}

template <int NT, int EPI, int BIAS, int RND>
__global__ void __launch_bounds__(256, 2)
wmma_gemm(const float* __restrict__ A, const float* __restrict__ B,
          const float* __restrict__ bias, float* __restrict__ C, int M, int N, int K) {
    extern __shared__ float sm[];
    gemm_body<NT, EPI, BIAS, RND>(A, B, bias, C, M, N, K, sm);
}

__global__ void __launch_bounds__(256, 2)
wmma_gemm_fuse3(const float* A0, const float* B0, float* C0,
                const float* A1, const float* B1, float* C1,
                const float* A2, const float* B2, float* C2) {
    extern __shared__ float sm[];
    if (blockIdx.z == 0)
        gemm_body<0, 0, 0, 1>(A0, B0, nullptr, C0, 1024, 1024, 1024, sm);
    else if (blockIdx.z == 1)
        gemm_body<0, 0, 0, 1>(A1, B1, nullptr, C1, 1024, 1024, 1024, sm);
    else
        gemm_body<0, 0, 0, 1>(A2, B2, nullptr, C2, 1024, 1024, 1024, sm);
}

// ==================== TF32 WMMA GEMM 128x256 NT (kv projection) ====================
__global__ void __launch_bounds__(256, 1)
wmma_gemm_kv(const float* __restrict__ A, const float* __restrict__ B,
             const float* __restrict__ bias, float* __restrict__ C,
             int M, int N, int K) {
    extern __shared__ float sm[];
    int tid = threadIdx.x;
    int wid = tid >> 5, lane = tid & 31;
    int warpRow = wid >> 2, warpCol = wid & 3;
    int bm = blockIdx.y * 128, bn = blockIdx.x * 256;

    uint32_t s_base = (uint32_t)__cvta_generic_to_shared(sm);
    int ra = tid >> 3, ca = (tid & 7) * 4;

    wmma::fragment<wmma::accumulator, 16, 16, 8, float> acc[4][4];
#pragma unroll
    for (int i = 0; i < 4; ++i)
#pragma unroll
        for (int j = 0; j < 4; ++j) wmma::fill_fragment(acc[i][j], 0.0f);

    const int KT = K >> 5;
    auto issue = [&](int stage, int k0) {
        uint32_t as = s_base + (uint32_t)(stage * 5120) * 4;
        uint32_t bs = s_base + (uint32_t)(10240 + stage * 10240) * 4;
#pragma unroll
        for (int it = 0; it < 4; ++it) {
            int r = ra + it * 32;
            cp16(as + (uint32_t)(r * 40 + ca) * 4, A + (size_t)(bm + r) * K + k0 + ca);
        }
#pragma unroll
        for (int it = 0; it < 8; ++it) {
            int r = ra + it * 32;
            cp16(bs + (uint32_t)(r * 40 + ca) * 4, B + (size_t)(bn + r) * K + k0 + ca);
        }
        CP_COMMIT();
    };

    issue(0, 0);
    for (int kt = 0; kt < KT; ++kt) {
        int stage = kt & 1;
        if (kt + 1 < KT) {
            issue(stage ^ 1, (kt + 1) * 32);
            CP_WAIT(1);
        } else {
            CP_WAIT(0);
        }
        __syncthreads();
        float* As = sm + stage * 5120;
        float* Bs = sm + 10240 + stage * 10240;
#pragma unroll
        for (int ks = 0; ks < 4; ++ks) {
            int kk = ks * 8;
            wmma::fragment<wmma::matrix_a, 16, 16, 8, wmma::precision::tf32, wmma::row_major> af[4];
            wmma::fragment<wmma::matrix_b, 16, 16, 8, wmma::precision::tf32, wmma::col_major> bf[4];
#pragma unroll
            for (int i = 0; i < 4; ++i)
                wmma::load_matrix_sync(af[i], &As[(warpRow * 64 + i * 16) * 40 + kk], 40);
#pragma unroll
            for (int j = 0; j < 4; ++j)
                wmma::load_matrix_sync(bf[j], &Bs[(warpCol * 64 + j * 16) * 40 + kk], 40);
#pragma unroll
            for (int i = 0; i < 4; ++i)
#pragma unroll
                for (int j = 0; j < 4; ++j) wmma::mma_sync(acc[i][j], af[i], bf[j], acc[i][j]);
        }
        __syncthreads();
    }

    float* st = &sm[wid * 384];
#pragma unroll
    for (int i = 0; i < 4; ++i) {
#pragma unroll
        for (int j = 0; j < 4; ++j) {
            wmma::store_matrix_sync(st, acc[i][j], 24, wmma::mem_row_major);
            __syncwarp();
            int row0 = bm + warpRow * 64 + i * 16;
            int col0 = bn + warpCol * 64 + j * 16;
            int r = lane >> 1, c8 = (lane & 1) * 8;
            float4 v0 = *(float4*)&st[r * 24 + c8];
            float4 v1 = *(float4*)&st[r * 24 + c8 + 4];
            const float* bp = bias + col0 + c8;
            v0.x = rtf(v0.x + bp[0]); v0.y = rtf(v0.y + bp[1]);
            v0.z = rtf(v0.z + bp[2]); v0.w = rtf(v0.w + bp[3]);
            v1.x = rtf(v1.x + bp[4]); v1.y = rtf(v1.y + bp[5]);
            v1.z = rtf(v1.z + bp[6]); v1.w = rtf(v1.w + bp[7]);
            float* cp = C + (size_t)(row0 + r) * N + col0 + c8;
            *(float4*)cp = v0;
            *(float4*)(cp + 4) = v1;
            __syncwarp();
        }
    }
}

// ==================== fused scores+softmax ====================
// grid (4, 128): x = l-chunk of 16 rows, y = bh. 256 threads.
// Smem (floats): S[16 x 2056] scores, Q[16 x 72], K stages 2 x [128 x 72].
// Per CTA: scores = Q(16x64) @ K(2048x64)^T in 16 chunks of 128 s; softmax in-CTA;
// probs written ONCE (tf32-rounded).
__global__ void __launch_bounds__(256)
scores_softmax_kernel(const float* __restrict__ qh, const float* __restrict__ kv,
                      const int* __restrict__ cmask, float* __restrict__ probs) {
    extern __shared__ float sm[];
    float* S = sm;                    // 16*2056 = 32896
    float* Q = sm + 32896;            // 16*72   = 1152
    float* K0 = sm + 34048;           // stages: 2 x 9216

    int bh = blockIdx.y;
    int b = bh >> 4, h = bh & 15;
    int l0 = blockIdx.x * 16;
    int tid = threadIdx.x, wid = tid >> 5, lane = tid & 31;

    // load Q tile (16x64)
    {
        int r = tid >> 4, c = (tid & 15) * 4;
        *(float4*)&Q[r * 72 + c] =
            *(const float4*)(qh + (size_t)(b * 64 + l0 + r) * 1024 + h * 64 + c);
    }

    uint32_t s_base = (uint32_t)__cvta_generic_to_shared(K0);
    int ra = tid >> 4, ca = (tid & 15) * 4;   // 16 rows per 256-thread pass
    auto issue = [&](int stage, int s0) {
        uint32_t ks = s_base + (uint32_t)(stage * 9216) * 4;
#pragma unroll
        for (int it = 0; it < 8; ++it) {
            int r = ra + it * 16;
            cp16(ks + (uint32_t)(r * 72 + ca) * 4,
                 kv + (size_t)(b * 2048 + s0 + r) * 2048 + h * 64 + ca);
        }
        CP_COMMIT();
    };

    issue(0, 0);
    __syncthreads();   // Q visible to all warps

    wmma::fragment<wmma::matrix_a, 16, 16, 8, wmma::precision::tf32, wmma::row_major> af[8];
#pragma unroll
    for (int ks = 0; ks < 8; ++ks) wmma::load_matrix_sync(af[ks], &Q[ks * 8], 72);

    for (int kt = 0; kt < 16; ++kt) {
        int stage = kt & 1;
        if (kt + 1 < 16) {
            issue(stage ^ 1, (kt + 1) * 128);
            CP_WAIT(1);
        } else {
            CP_WAIT(0);
        }
        __syncthreads();
        float* Ks = K0 + stage * 9216;
        wmma::fragment<wmma::accumulator, 16, 16, 8, float> acc;
        wmma::fill_fragment(acc, 0.0f);
#pragma unroll
        for (int ks = 0; ks < 8; ++ks) {
            wmma::fragment<wmma::matrix_b, 16, 16, 8, wmma::precision::tf32, wmma::col_major> bf;
            wmma::load_matrix_sync(bf, &Ks[(wid * 16) * 72 + ks * 8], 72);
            wmma::mma_sync(acc, af[ks], bf, acc);
        }
        wmma::store_matrix_sync(&S[kt * 128 + wid * 16], acc, 2056, wmma::mem_row_major);
        __syncthreads();
    }

    // in-CTA softmax: warp per row (2 rows per warp)
    const float NEG = __int_as_float(0xff800000);
    const int* mrow = cmask + b * 2048;
#pragma unroll
    for (int rr = 0; rr < 2; ++rr) {
        int r = wid + rr * 8;
        float* Srow = S + r * 2056;
        // pass 1: mask+scale into smem, running max
        float mx = NEG;
        for (int i = lane; i < 512; i += 32) {
            float4 v = *(float4*)&Srow[i * 4];
            int4 mm = *(const int4*)&mrow[i * 4];
            v.x = mm.x ? v.x * 0.125f : NEG;
            v.y = mm.y ? v.y * 0.125f : NEG;
            v.z = mm.z ? v.z * 0.125f : NEG;
            v.w = mm.w ? v.w * 0.125f : NEG;
            *(float4*)&Srow[i * 4] = v;
            mx = fmaxf(mx, fmaxf(fmaxf(v.x, v.y), fmaxf(v.z, v.w)));
        }
#pragma unroll
        for (int o = 16; o > 0; o >>= 1) mx = fmaxf(mx, __shfl_xor_sync(0xffffffffu, mx, o));
        // pass 2: exp + sum (store exp back)
        float s = 0.f;
        for (int i = lane; i < 512; i += 32) {
            float4 v = *(float4*)&Srow[i * 4];
            v.x = expf(v.x - mx); v.y = expf(v.y - mx);
            v.z = expf(v.z - mx); v.w = expf(v.w - mx);
            *(float4*)&Srow[i * 4] = v;
            s += (v.x + v.y) + (v.z + v.w);
        }
#pragma unroll
        for (int o = 16; o > 0; o >>= 1) s += __shfl_xor_sync(0xffffffffu, s, o);
        float inv = 1.0f / s;
        // pass 3: normalize, round, write probs once
        float* prow = probs + ((size_t)bh * 64 + l0 + r) * 2048;
        for (int i = lane; i < 512; i += 32) {
            float4 v = *(float4*)&Srow[i * 4];
            v.x = rtf(v.x * inv); v.y = rtf(v.y * inv);
            v.z = rtf(v.z * inv); v.w = rtf(v.w * inv);
            *(float4*)&prow[i * 4] = v;
        }
    }
}

// ==================== attn split-K: partial P @ V ====================
// grid (128, 4): x = bh, y = s-split (512 each). Dyn smem 73728 B.
__global__ void __launch_bounds__(256)
attn_part_kernel(const float* __restrict__ probs, const float* __restrict__ kv,
                 float* __restrict__ part) {
    extern __shared__ float sm[];
    int bh = blockIdx.x;
    int b = bh >> 4, h = bh & 15;
    int base_s = blockIdx.y * 512;
    int tid = threadIdx.x, wid = tid >> 5, lane = tid & 31;
    int warpRow = wid >> 1, warpCol = wid & 1;

    uint32_t s_base = (uint32_t)__cvta_generic_to_shared(sm);
    int ra = tid >> 4, ca = (tid & 15) * 4;

    wmma::fragment<wmma::accumulator, 16, 16, 8, float> acc[2];
    wmma::fill_fragment(acc[0], 0.0f);
    wmma::fill_fragment(acc[1], 0.0f);

    auto issue = [&](int stage, int s0) {
        uint32_t ps = s_base + (uint32_t)(stage * 4608) * 4;
        uint32_t vs = s_base + (uint32_t)(9216 + stage * 4608) * 4;
#pragma unroll
        for (int it = 0; it < 4; ++it) {
            int r = ra + it * 16;
            cp16(ps + (uint32_t)(r * 72 + ca) * 4,
                 probs + ((size_t)bh * 64 + r) * 2048 + s0 + ca);
            cp16(vs + (uint32_t)(r * 72 + ca) * 4,
                 kv + (size_t)(b * 2048 + s0 + r) * 2048 + 1024 + h * 64 + ca);
        }
        CP_COMMIT();
    };

    issue(0, base_s);
    for (int kt = 0; kt < 8; ++kt) {
        int stage = kt & 1;
        if (kt + 1 < 8) {
            issue(stage ^ 1, base_s + (kt + 1) * 64);
            CP_WAIT(1);
        } else {
            CP_WAIT(0);
        }
        __syncthreads();
        float* Ps = sm + stage * 4608;
        float* Vs = sm + 9216 + stage * 4608;
#pragma unroll
        for (int ks = 0; ks < 8; ++ks) {
            int kk = ks * 8;
            wmma::fragment<wmma::matrix_a, 16, 16, 8, wmma::precision::tf32, wmma::row_major> af;
            wmma::fragment<wmma::matrix_b, 16, 16, 8, wmma::precision::tf32, wmma::row_major> bf[2];
            wmma::load_matrix_sync(af, &Ps[(warpRow * 16) * 72 + kk], 72);
#pragma unroll
            for (int j = 0; j < 2; ++j)
                wmma::load_matrix_sync(bf[j], &Vs[kk * 72 + warpCol * 32 + j * 16], 72);
            wmma::mma_sync(acc[0], af, bf[0], acc[0]);
            wmma::mma_sync(acc[1], af, bf[1], acc[1]);
        }
        __syncthreads();
    }

    float* pout = part + (size_t)blockIdx.y * 524288;
    float* st = &sm[wid * 384];
#pragma unroll
    for (int j = 0; j < 2; ++j) {
        wmma::store_matrix_sync(st, acc[j], 24, wmma::mem_row_major);
        __syncwarp();
        int r = lane >> 1, c8 = (lane & 1) * 8;
        int l = warpRow * 16 + r;
        int d0 = warpCol * 32 + j * 16 + c8;
        float4 v0 = *(float4*)&st[r * 24 + c8];
        float4 v1 = *(float4*)&st[r * 24 + c8 + 4];
        float* ap = pout + (size_t)(b * 64 + l) * 1024 + h * 64 + d0;
        *(float4*)ap = v0;
        *(float4*)(ap + 4) = v1;
        __syncwarp();
    }
}

// reduce 4 partials -> attn (tf32-rounded)
__global__ void attn_reduce_kernel(const float* __restrict__ part, float* __restrict__ attn) {
    int i = blockIdx.x * 256 + threadIdx.x;   // float4 units, 131072 total
    float4 a = ((const float4*)part)[i];
    float4 b = ((const float4*)(part + 524288))[i];
    float4 c = ((const float4*)(part + 1048576))[i];
    float4 d = ((const float4*)(part + 1572864))[i];
    float4 o;
    o.x = rtf(((a.x + b.x) + (c.x + d.x)));
    o.y = rtf(((a.y + b.y) + (c.y + d.y)));
    o.z = rtf(((a.z + b.z) + (c.z + d.z)));
    o.w = rtf(((a.w + b.w) + (c.w + d.w)));
    ((float4*)attn)[i] = o;
}

// ---------------- residual add + LayerNorm (optional rounded copy) ----------------
template <int WR>
__global__ void add_ln_kernel(const float* __restrict__ a, const float* __restrict__ b2,
                              const float* __restrict__ g, const float* __restrict__ bet,
                              float* __restrict__ out, float* __restrict__ out_r) {
    int row = blockIdx.x, tid = threadIdx.x;
    const float4* a4 = (const float4*)(a + (size_t)row * 1024);
    const float4* b4 = (const float4*)(b2 + (size_t)row * 1024);
    float4 va = a4[tid], vb = b4[tid];
    float4 x;
    x.x = va.x + vb.x; x.y = va.y + vb.y; x.z = va.z + vb.z; x.w = va.w + vb.w;
    float s = (x.x + x.y) + (x.z + x.w);
    float sq = x.x * x.x + x.y * x.y + x.z * x.z + x.w * x.w;
    __shared__ float r1[256], r2[256];
    r1[tid] = s; r2[tid] = sq;
    __syncthreads();
    for (int st = 128; st > 0; st >>= 1) {
        if (tid < st) { r1[tid] += r1[tid + st]; r2[tid] += r2[tid + st]; }
        __syncthreads();
    }
    float mean = r1[0] * (1.0f / 1024.0f);
    float var = r2[0] * (1.0f / 1024.0f) - mean * mean;
    float rstd = rsqrtf(var + 1e-5f);
    float4 gg = ((const float4*)g)[tid], bb = ((const float4*)bet)[tid];
    float4 o;
    o.x = (x.x - mean) * rstd * gg.x + bb.x;
    o.y = (x.y - mean) * rstd * gg.y + bb.y;
    o.z = (x.z - mean) * rstd * gg.z + bb.z;
    o.w = (x.w - mean) * rstd * gg.w + bb.w;
    ((float4*)(out + (size_t)row * 1024))[tid] = o;
    if (WR) {
        float4 q;
        q.x = rtf(o.x); q.y = rtf(o.y); q.z = rtf(o.z); q.w = rtf(o.w);
        ((float4*)(out_r + (size_t)row * 1024))[tid] = q;
    }
}

// ---------------- attn_weights = mean over heads of probs ----------------
__global__ void mean_heads_kernel(const float* __restrict__ probs, float* __restrict__ aw) {
    int i = blockIdx.x * 256 + threadIdx.x;
    int s4 = i & 511;
    int l = (i >> 9) & 63;
    int b = i >> 15;
    float4 acc = {0.f, 0.f, 0.f, 0.f};
#pragma unroll
    for (int h = 0; h < 16; ++h) {
        float4 p = *(const float4*)(probs + ((size_t)(b * 16 + h) * 64 + l) * 2048 + s4 * 4);
        acc.x += p.x; acc.y += p.y; acc.z += p.z; acc.w += p.w;
    }
    const float inv = 1.0f / 16.0f;
    acc.x *= inv; acc.y *= inv; acc.z *= inv; acc.w *= inv;
    *(float4*)(aw + ((size_t)(b * 64 + l) * 2048) + s4 * 4) = acc;
}

// ---------------- launch ----------------
extern "C" void kernel_launch(void* const* d_in, const int* in_sizes, int n_in,
                              void* d_out, int out_size) {
    (void)in_sizes; (void)n_in; (void)out_size;
    const float* latents = (const float*)d_in[0];
    const float* context = (const float*)d_in[1];
    const int* cmask = (const int*)d_in[2];
    const float* q_w = (const float*)d_in[3];
    const float* q_b = (const float*)d_in[4];
    const float* k_w = (const float*)d_in[5];
    const float* k_b = (const float*)d_in[6];
    const float* v_w = (const float*)d_in[7];
    const float* v_b = (const float*)d_in[8];
    const float* in_wq = (const float*)d_in[9];
    const float* in_bq = (const float*)d_in[10];
    const float* in_wk = (const float*)d_in[11];
    const float* in_bk = (const float*)d_in[12];
    const float* in_wv = (const float*)d_in[13];
    const float* in_bv = (const float*)d_in[14];
    const float* out_w = (const float*)d_in[15];
    const float* out_b = (const float*)d_in[16];
    const float* ln1_g = (const float*)d_in[17];
    const float* ln1_b = (const float*)d_in[18];
    const float* ln2_g = (const float*)d_in[19];
    const float* ln2_b = (const float*)d_in[20];
    const float* ff_w1 = (const float*)d_in[21];
    const float* ff_b1 = (const float*)d_in[22];
    const float* ff_w2 = (const float*)d_in[23];
    const float* ff_b2 = (const float*)d_in[24];

    float* out = (float*)d_out;
    float* aw_out = out + 512 * 1024;

    void* p;
    cudaGetSymbolAddress(&p, g_fuse6);  float* fuse6 = (float*)p;
    cudaGetSymbolAddress(&p, g_ctx_r);  float* ctx_r = (float*)p;
    cudaGetSymbolAddress(&p, g_lat_r);  float* lat_r = (float*)p;
    cudaGetSymbolAddress(&p, g_outw_r); float* outw_r = (float*)p;
    cudaGetSymbolAddress(&p, g_ffw1_r); float* ffw1_r = (float*)p;
    cudaGetSymbolAddress(&p, g_ffw2_r); float* ffw2_r = (float*)p;
    cudaGetSymbolAddress(&p, g_Wq);     float* Wq = (float*)p;
    cudaGetSymbolAddress(&p, g_Wkv);    float* Wkv = (float*)p;
    cudaGetSymbolAddress(&p, g_bq);     float* bq = (float*)p;
    cudaGetSymbolAddress(&p, g_bkv);    float* bkv = (float*)p;
    cudaGetSymbolAddress(&p, g_qh);     float* qh = (float*)p;
    cudaGetSymbolAddress(&p, g_kv);     float* kvb = (float*)p;
    cudaGetSymbolAddress(&p, g_probs);  float* probs = (float*)p;
    cudaGetSymbolAddress(&p, g_part);   float* part = (float*)p;
    cudaGetSymbolAddress(&p, g_attn);   float* attn = (float*)p;
    cudaGetSymbolAddress(&p, g_x);      float* xb = (float*)p;
    cudaGetSymbolAddress(&p, g_xr);     float* xr = (float*)p;
    cudaGetSymbolAddress(&p, g_h1);     float* h1 = (float*)p;

    const int SMEM = 81920;
    cudaFuncSetAttribute(wmma_gemm_fuse3, cudaFuncAttributeMaxDynamicSharedMemorySize, SMEM);
    cudaFuncSetAttribute(wmma_gemm<1, 0, 1, 1>, cudaFuncAttributeMaxDynamicSharedMemorySize, SMEM);
    cudaFuncSetAttribute(wmma_gemm<1, 0, 1, 0>, cudaFuncAttributeMaxDynamicSharedMemorySize, SMEM);
    cudaFuncSetAttribute(wmma_gemm<1, 1, 1, 1>, cudaFuncAttributeMaxDynamicSharedMemorySize, SMEM);
    cudaFuncSetAttribute(wmma_gemm_kv, cudaFuncAttributeMaxDynamicSharedMemorySize, 122880);
    cudaFuncSetAttribute(scores_softmax_kernel, cudaFuncAttributeMaxDynamicSharedMemorySize, 209920);
    cudaFuncSetAttribute(attn_part_kernel, cudaFuncAttributeMaxDynamicSharedMemorySize, 73728);

    // ---- pre-round operands to tf32 (RNE) ----
    round6_kernel<<<dim3(1024, 6), 256>>>((const float4*)in_wq, (const float4*)q_w,
                                          (const float4*)in_wk, (const float4*)k_w,
                                          (const float4*)in_wv, (const float4*)v_w,
                                          (float4*)fuse6);
    round_tf32_kernel<<<16384, 256>>>((const float4*)context, (float4*)ctx_r, 4194304);
    round_tf32_kernel<<<512, 256>>>((const float4*)latents, (float4*)lat_r, 131072);
    round_tf32_kernel<<<1024, 256>>>((const float4*)out_w, (float4*)outw_r, 262144);
    round_tf32_kernel<<<4096, 256>>>((const float4*)ff_w1, (float4*)ffw1_r, 1048576);
    round_tf32_kernel<<<4096, 256>>>((const float4*)ff_w2, (float4*)ffw2_r, 1048576);

    // ---- fused weights/biases, batched ----
    fuse_bias_kernel<<<1024, 256>>>(in_wq, q_b, in_bq, bq);
    fuse_bias_kernel<<<1024, 256>>>(in_wk, k_b, in_bk, bkv);
    fuse_bias_kernel<<<1024, 256>>>(in_wv, v_b, in_bv, bkv + 1024);
    const size_t MM = 1024 * 1024;
    wmma_gemm_fuse3<<<dim3(8, 8, 3), 256, SMEM>>>(
        fuse6 + 0 * MM, fuse6 + 1 * MM, Wq,
        fuse6 + 2 * MM, fuse6 + 3 * MM, Wkv,
        fuse6 + 4 * MM, fuse6 + 5 * MM, Wkv + 1024 * 1024);

    // ---- projections ----
    wmma_gemm<1, 0, 1, 1><<<dim3(8, 4), 256, SMEM>>>(lat_r, Wq, bq, qh, 512, 1024, 1024);
    wmma_gemm_kv<<<dim3(8, 128), 256, 122880>>>(ctx_r, Wkv, bkv, kvb, 16384, 2048, 1024);

    // ---- attention: fused scores+softmax, split-K P.V ----
    scores_softmax_kernel<<<dim3(4, 128), 256, 209920>>>(qh, kvb, cmask, probs);
    attn_part_kernel<<<dim3(128, 4), 256, 73728>>>(probs, kvb, part);
    attn_reduce_kernel<<<512, 256>>>(part, attn);

    // ---- out projection (reuse qh for attn_out) ----
    wmma_gemm<1, 0, 1, 0><<<dim3(8, 4), 256, SMEM>>>(attn, outw_r, out_b, qh, 512, 1024, 1024);

    // ---- LN1 (exact + rounded copy) ----
    add_ln_kernel<1><<<512, 256>>>(latents, qh, ln1_g, ln1_b, xb, xr);

    // ---- FFN ----
    wmma_gemm<1, 1, 1, 1><<<dim3(32, 4), 256, SMEM>>>(xr, ffw1_r, ff_b1, h1, 512, 4096, 1024);
    wmma_gemm<1, 0, 1, 0><<<dim3(8, 4), 256, SMEM>>>(h1, ffw2_r, ff_b2, attn, 512, 1024, 4096);

    // ---- LN2 -> out ----
    add_ln_kernel<0><<<512, 256>>>(xb, attn, ln2_g, ln2_b, out, nullptr);

    // ---- attn_weights -> second output region ----
    mean_heads_kernel<<<1024, 256>>>(probs, aw_out);
}

// round 8
// speedup vs baseline: 1.1180x; 1.1180x over previous
#include <cuda_runtime.h>
#include <mma.h>
#include <math.h>
#include <stdint.h>

using namespace nvcuda;

// Shapes: B=8, L=64, S=2048, D=1024, C=1024, H=16, HD=64

// ---------------- device scratch ----------------
__device__ float g_fuse6[6 * 1024 * 1024];   // rounded fusion inputs
__device__ float g_ctx_r[16384 * 1024];      // rounded context
__device__ float g_lat_r[512 * 1024];        // rounded latents
__device__ float g_outw_r[1024 * 1024];
__device__ float g_ffw1_r[4096 * 1024];
__device__ float g_ffw2_r[1024 * 4096];
__device__ float g_Wq[1024 * 1024];          // fused+rounded q weight
__device__ float g_Wkv[2048 * 1024];         // fused+rounded k|v weights
__device__ float g_bq[1024];
__device__ float g_bkv[2048];
__device__ float g_qh[512 * 1024];           // q heads (rounded); reused for attn_out
__device__ float g_kv[16384 * 2048];         // kh | vh interleaved per row (rounded)
__device__ float g_probs[8192 * 2048];       // [B,H,L,S] (rounded post-softmax)
__device__ float g_part[4 * 512 * 1024];     // attn split-K partials
__device__ float g_attn[512 * 1024];         // attn concat (rounded); reused for ff2 out
__device__ float g_x[512 * 1024];            // post-LN1 exact
__device__ float g_xr[512 * 1024];           // post-LN1 rounded
__device__ float g_h1[512 * 4096];           // ff hidden (rounded)

__device__ __forceinline__ float gelu_exact(float x) {
    return 0.5f * x * (1.0f + erff(x * 0.70710678118654752f));
}
__device__ __forceinline__ float rtf(float x) {
    float y;
    asm("cvt.rna.tf32.f32 %0, %1;" : "=f"(y) : "f"(x));
    return y;
}
__device__ __forceinline__ void cp16(uint32_t dst, const void* src) {
    asm volatile("cp.async.cg.shared.global [%0], [%1], 16;\n" ::"r"(dst), "l"(src));
}
#define CP_COMMIT() asm volatile("cp.async.commit_group;\n" ::)
#define CP_WAIT(n) asm volatile("cp.async.wait_group %0;\n" ::"n"(n))

// ---------------- rounding kernels ----------------
__global__ void round6_kernel(const float4* a0, const float4* a1, const float4* a2,
                              const float4* a3, const float4* a4, const float4* a5,
                              float4* __restrict__ out) {
    const float4* srcs[6] = {a0, a1, a2, a3, a4, a5};
    int z = blockIdx.y;
    int i = blockIdx.x * 256 + threadIdx.x;
    float4 v = srcs[z][i];
    v.x = rtf(v.x); v.y = rtf(v.y); v.z = rtf(v.z); v.w = rtf(v.w);
    out[(size_t)z * 262144 + i] = v;
}

// single launch rounding of 5 regions (segmented)
__global__ void round_all_kernel(const float4* s0, float4* d0, int n0,
                                 const float4* s1, float4* d1, int n1,
                                 const float4* s2, float4* d2, int n2,
                                 const float4* s3, float4* d3, int n3,
                                 const float4* s4, float4* d4, int n4c) {
    int i = blockIdx.x * 256 + threadIdx.x;
    const float4* s;
    float4* d;
    int off;
    if (i < n0) { s = s0; d = d0; off = i; }
    else if ((i -= n0) < n1) { s = s1; d = d1; off = i; }
    else if ((i -= n1) < n2) { s = s2; d = d2; off = i; }
    else if ((i -= n2) < n3) { s = s3; d = d3; off = i; }
    else if ((i -= n3) < n4c) { s = s4; d = d4; off = i; }
    else return;
    float4 v = s[off];
    v.x = rtf(v.x); v.y = rtf(v.y); v.z = rtf(v.z); v.w = rtf(v.w);
    d[off] = v;
}

// ---------------- bias fusion ----------------
__global__ void fuse_bias_kernel(const float* __restrict__ W, const float* __restrict__ bin,
                                 const float* __restrict__ badd, float* __restrict__ bout) {
    int o = blockIdx.x;
    float s = 0.f;
    for (int i = threadIdx.x; i < 1024; i += 256) s += W[o * 1024 + i] * bin[i];
    __shared__ float red[256];
    red[threadIdx.x] = s;
    __syncthreads();
    for (int st = 128; st > 0; st >>= 1) {
        if (threadIdx.x < st) red[threadIdx.x] += red[threadIdx.x + st];
        __syncthreads();
    }
    if (threadIdx.x == 0) bout[o] = red[0] + badd[o];
}

// ==================== TF32 WMMA GEMM 128x128 (weight fusion) ====================
template <int NT, int EPI, int BIAS, int RND>
__device__ __forceinline__ void gemm_body(const float* __restrict__ A, const float* __restrict__ B,
                                          const float* __restrict__ bias, float* __restrict__ C,
                                          int M, int N, int K, float* sm) {
    int tid = threadIdx.x;
    int wid = tid >> 5, lane = tid & 31;
    int warpRow = wid >> 2, warpCol = wid & 3;
    int bm = blockIdx.y * 128, bn = blockIdx.x * 128;

    uint32_t s_base = (uint32_t)__cvta_generic_to_shared(sm);
    int ra = tid >> 3, ca = (tid & 7) * 4;
    int kb = tid >> 5, cb = (tid & 31) * 4;

    wmma::fragment<wmma::accumulator, 16, 16, 8, float> acc[4][2];
#pragma unroll
    for (int i = 0; i < 4; ++i)
#pragma unroll
        for (int j = 0; j < 2; ++j) wmma::fill_fragment(acc[i][j], 0.0f);

    const int KT = K >> 5;
    auto issue = [&](int stage, int k0) {
        uint32_t as = s_base + (uint32_t)(stage * 5120) * 4;
        uint32_t bs = s_base + (uint32_t)(10240 + stage * 5120) * 4;
#pragma unroll
        for (int it = 0; it < 4; ++it) {
            int r = ra + it * 32;
            cp16(as + (uint32_t)(r * 40 + ca) * 4, A + (size_t)(bm + r) * K + k0 + ca);
        }
        if (NT) {
#pragma unroll
            for (int it = 0; it < 4; ++it) {
                int r = ra + it * 32;
                cp16(bs + (uint32_t)(r * 40 + ca) * 4, B + (size_t)(bn + r) * K + k0 + ca);
            }
        } else {
#pragma unroll
            for (int it = 0; it < 4; ++it) {
                int kk = kb + it * 8;
                cp16(bs + (uint32_t)(kk * 136 + cb) * 4, B + (size_t)(k0 + kk) * N + bn + cb);
            }
        }
        CP_COMMIT();
    };

    issue(0, 0);
    for (int kt = 0; kt < KT; ++kt) {
        int stage = kt & 1;
        if (kt + 1 < KT) {
            issue(stage ^ 1, (kt + 1) * 32);
            CP_WAIT(1);
        } else {
            CP_WAIT(0);
        }
        __syncthreads();
        float* As = sm + stage * 5120;
        float* Bs = sm + 10240 + stage * 5120;
#pragma unroll
        for (int ks = 0; ks < 4; ++ks) {
            int kk = ks * 8;
            wmma::fragment<wmma::matrix_a, 16, 16, 8, wmma::precision::tf32, wmma::row_major> af[4];
#pragma unroll
            for (int i = 0; i < 4; ++i)
                wmma::load_matrix_sync(af[i], &As[(warpRow * 64 + i * 16) * 40 + kk], 40);
            if (NT) {
                wmma::fragment<wmma::matrix_b, 16, 16, 8, wmma::precision::tf32, wmma::col_major> bf[2];
#pragma unroll
                for (int j = 0; j < 2; ++j)
                    wmma::load_matrix_sync(bf[j], &Bs[(warpCol * 32 + j * 16) * 40 + kk], 40);
#pragma unroll
                for (int i = 0; i < 4; ++i)
#pragma unroll
                    for (int j = 0; j < 2; ++j) wmma::mma_sync(acc[i][j], af[i], bf[j], acc[i][j]);
            } else {
                wmma::fragment<wmma::matrix_b, 16, 16, 8, wmma::precision::tf32, wmma::row_major> bf[2];
#pragma unroll
                for (int j = 0; j < 2; ++j)
                    wmma::load_matrix_sync(bf[j], &Bs[kk * 136 + warpCol * 32 + j * 16], 136);
#pragma unroll
                for (int i = 0; i < 4; ++i)
#pragma unroll
                    for (int j = 0; j < 2; ++j) wmma::mma_sync(acc[i][j], af[i], bf[j], acc[i][j]);
            }
        }
        __syncthreads();
    }

    float* st = &sm[wid * 384];
#pragma unroll
    for (int i = 0; i < 4; ++i) {
#pragma unroll
        for (int j = 0; j < 2; ++j) {
            wmma::store_matrix_sync(st, acc[i][j], 24, wmma::mem_row_major);
            __syncwarp();
            int row0 = bm + warpRow * 64 + i * 16;
            int col0 = bn + warpCol * 32 + j * 16;
            int r = lane >> 1, c8 = (lane & 1) * 8;
            float4 v0 = *(float4*)&st[r * 24 + c8];
            float4 v1 = *(float4*)&st[r * 24 + c8 + 4];
            if (BIAS) {
                const float* bp = bias + col0 + c8;
                v0.x += bp[0]; v0.y += bp[1]; v0.z += bp[2]; v0.w += bp[3];
                v1.x += bp[4]; v1.y += bp[5]; v1.z += bp[6]; v1.w += bp[7];
            }
            if (EPI) {
                v0.x = gelu_exact(v0.x); v0.y = gelu_exact(v0.y);
                v0.z = gelu_exact(v0.z); v0.w = gelu_exact(v0.w);
                v1.x = gelu_exact(v1.x); v1.y = gelu_exact(v1.y);
                v1.z = gelu_exact(v1.z); v1.w = gelu_exact(v1.w);
            }
            if (RND) {
                v0.x = rtf(v0.x); v0.y = rtf(v0.y); v0.z = rtf(v0.z); v0.w = rtf(v0.w);
                v1.x = rtf(v1.x); v1.y = rtf(v1.y); v1.z = rtf(v1.z); v1.w = rtf(v1.w);
            }
            float* cp = C + (size_t)(row0 + r) * N + col0 + c8;
            *(float4*)cp = v0;
            *(float4*)(cp + 4) = v1;
            __syncwarp();
        }
    }
}

__global__ void __launch_bounds__(256, 2)
wmma_gemm_fuse3(const float* A0, const float* B0, float* C0,
                const float* A1, const float* B1, float* C1,
                const float* A2, const float* B2, float* C2) {
    extern __shared__ float sm[];
    if (blockIdx.z == 0)
        gemm_body<0, 0, 0, 1>(A0, B0, nullptr, C0, 1024, 1024, 1024, sm);
    else if (blockIdx.z == 1)
        gemm_body<0, 0, 0, 1>(A1, B1, nullptr, C1, 1024, 1024, 1024, sm);
    else
        gemm_body<0, 0, 0, 1>(A2, B2, nullptr, C2, 1024, 1024, 1024, sm);
}

// ==================== TF32 WMMA GEMM 64x128 NT (small-M GEMMs) ====================
// 8 warps as 2x4, warp tile 32x32. Smem: A 2x2560, B 2x5120 fl = 60KB.
template <int EPI, int BIAS, int RND>
__global__ void __launch_bounds__(256, 2)
wmma_gemm_small(const float* __restrict__ A, const float* __restrict__ B,
                const float* __restrict__ bias, float* __restrict__ C,
                int M, int N, int K) {
    extern __shared__ float sm[];
    int tid = threadIdx.x;
    int wid = tid >> 5, lane = tid & 31;
    int warpRow = wid >> 2, warpCol = wid & 3;
    int bm = blockIdx.y * 64, bn = blockIdx.x * 128;

    uint32_t s_base = (uint32_t)__cvta_generic_to_shared(sm);
    int ra = tid >> 3, ca = (tid & 7) * 4;

    wmma::fragment<wmma::accumulator, 16, 16, 8, float> acc[2][2];
#pragma unroll
    for (int i = 0; i < 2; ++i)
#pragma unroll
        for (int j = 0; j < 2; ++j) wmma::fill_fragment(acc[i][j], 0.0f);

    const int KT = K >> 5;
    auto issue = [&](int stage, int k0) {
        uint32_t as = s_base + (uint32_t)(stage * 2560) * 4;
        uint32_t bs = s_base + (uint32_t)(5120 + stage * 5120) * 4;
#pragma unroll
        for (int it = 0; it < 2; ++it) {
            int r = ra + it * 32;
            cp16(as + (uint32_t)(r * 40 + ca) * 4, A + (size_t)(bm + r) * K + k0 + ca);
        }
#pragma unroll
        for (int it = 0; it < 4; ++it) {
            int r = ra + it * 32;
            cp16(bs + (uint32_t)(r * 40 + ca) * 4, B + (size_t)(bn + r) * K + k0 + ca);
        }
        CP_COMMIT();
    };

    issue(0, 0);
    for (int kt = 0; kt < KT; ++kt) {
        int stage = kt & 1;
        if (kt + 1 < KT) {
            issue(stage ^ 1, (kt + 1) * 32);
            CP_WAIT(1);
        } else {
            CP_WAIT(0);
        }
        __syncthreads();
        float* As = sm + stage * 2560;
        float* Bs = sm + 5120 + stage * 5120;
#pragma unroll
        for (int ks = 0; ks < 4; ++ks) {
            int kk = ks * 8;
            wmma::fragment<wmma::matrix_a, 16, 16, 8, wmma::precision::tf32, wmma::row_major> af[2];
            wmma::fragment<wmma::matrix_b, 16, 16, 8, wmma::precision::tf32, wmma::col_major> bf[2];
#pragma unroll
            for (int i = 0; i < 2; ++i)
                wmma::load_matrix_sync(af[i], &As[(warpRow * 32 + i * 16) * 40 + kk], 40);
#pragma unroll
            for (int j = 0; j < 2; ++j)
                wmma::load_matrix_sync(bf[j], &Bs[(warpCol * 32 + j * 16) * 40 + kk], 40);
#pragma unroll
            for (int i = 0; i < 2; ++i)
#pragma unroll
                for (int j = 0; j < 2; ++j) wmma::mma_sync(acc[i][j], af[i], bf[j], acc[i][j]);
        }
        __syncthreads();
    }

    float* st = &sm[wid * 384];
#pragma unroll
    for (int i = 0; i < 2; ++i) {
#pragma unroll
        for (int j = 0; j < 2; ++j) {
            wmma::store_matrix_sync(st, acc[i][j], 24, wmma::mem_row_major);
            __syncwarp();
            int row0 = bm + warpRow * 32 + i * 16;
            int col0 = bn + warpCol * 32 + j * 16;
            int r = lane >> 1, c8 = (lane & 1) * 8;
            float4 v0 = *(float4*)&st[r * 24 + c8];
            float4 v1 = *(float4*)&st[r * 24 + c8 + 4];
            if (BIAS) {
                const float* bp = bias + col0 + c8;
                v0.x += bp[0]; v0.y += bp[1]; v0.z += bp[2]; v0.w += bp[3];
                v1.x += bp[4]; v1.y += bp[5]; v1.z += bp[6]; v1.w += bp[7];
            }
            if (EPI) {
                v0.x = gelu_exact(v0.x); v0.y = gelu_exact(v0.y);
                v0.z = gelu_exact(v0.z); v0.w = gelu_exact(v0.w);
                v1.x = gelu_exact(v1.x); v1.y = gelu_exact(v1.y);
                v1.z = gelu_exact(v1.z); v1.w = gelu_exact(v1.w);
            }
            if (RND) {
                v0.x = rtf(v0.x); v0.y = rtf(v0.y); v0.z = rtf(v0.z); v0.w = rtf(v0.w);
                v1.x = rtf(v1.x); v1.y = rtf(v1.y); v1.z = rtf(v1.z); v1.w = rtf(v1.w);
            }
            float* cp = C + (size_t)(row0 + r) * N + col0 + c8;
            *(float4*)cp = v0;
            *(float4*)(cp + 4) = v1;
            __syncwarp();
        }
    }
}

// ==================== TF32 WMMA GEMM 128x256 NT, 3-stage (kv projection) ============
// A stages 3x5120, B stages 3x10240 fl = 184320 B.
__global__ void __launch_bounds__(256, 1)
wmma_gemm_kv(const float* __restrict__ A, const float* __restrict__ B,
             const float* __restrict__ bias, float* __restrict__ C,
             int M, int N, int K) {
    extern __shared__ float sm[];
    int tid = threadIdx.x;
    int wid = tid >> 5, lane = tid & 31;
    int warpRow = wid >> 2, warpCol = wid & 3;
    int bm = blockIdx.y * 128, bn = blockIdx.x * 256;

    uint32_t s_base = (uint32_t)__cvta_generic_to_shared(sm);
    int ra = tid >> 3, ca = (tid & 7) * 4;

    wmma::fragment<wmma::accumulator, 16, 16, 8, float> acc[4][4];
#pragma unroll
    for (int i = 0; i < 4; ++i)
#pragma unroll
        for (int j = 0; j < 4; ++j) wmma::fill_fragment(acc[i][j], 0.0f);

    const int KT = K >> 5;   // 32
    auto issue = [&](int stage, int k0) {
        uint32_t as = s_base + (uint32_t)(stage * 5120) * 4;
        uint32_t bs = s_base + (uint32_t)(15360 + stage * 10240) * 4;
#pragma unroll
        for (int it = 0; it < 4; ++it) {
            int r = ra + it * 32;
            cp16(as + (uint32_t)(r * 40 + ca) * 4, A + (size_t)(bm + r) * K + k0 + ca);
        }
#pragma unroll
        for (int it = 0; it < 8; ++it) {
            int r = ra + it * 32;
            cp16(bs + (uint32_t)(r * 40 + ca) * 4, B + (size_t)(bn + r) * K + k0 + ca);
        }
        CP_COMMIT();
    };

    issue(0, 0);
    issue(1, 32);
    int stage = 0;
    for (int kt = 0; kt < KT; ++kt) {
        if (kt + 2 < KT) {
            int s2 = (kt + 2) % 3;
            issue(s2, (kt + 2) * 32);
            CP_WAIT(2);
        } else if (kt + 1 < KT) {
            CP_WAIT(1);
        } else {
            CP_WAIT(0);
        }
        __syncthreads();
        float* As = sm + stage * 5120;
        float* Bs = sm + 15360 + stage * 10240;
#pragma unroll
        for (int ks = 0; ks < 4; ++ks) {
            int kk = ks * 8;
            wmma::fragment<wmma::matrix_a, 16, 16, 8, wmma::precision::tf32, wmma::row_major> af[4];
            wmma::fragment<wmma::matrix_b, 16, 16, 8, wmma::precision::tf32, wmma::col_major> bf[4];
#pragma unroll
            for (int i = 0; i < 4; ++i)
                wmma::load_matrix_sync(af[i], &As[(warpRow * 64 + i * 16) * 40 + kk], 40);
#pragma unroll
            for (int j = 0; j < 4; ++j)
                wmma::load_matrix_sync(bf[j], &Bs[(warpCol * 64 + j * 16) * 40 + kk], 40);
#pragma unroll
            for (int i = 0; i < 4; ++i)
#pragma unroll
                for (int j = 0; j < 4; ++j) wmma::mma_sync(acc[i][j], af[i], bf[j], acc[i][j]);
        }
        __syncthreads();
        stage = (stage + 1 == 3) ? 0 : stage + 1;
    }

    float* st = &sm[wid * 384];
#pragma unroll
    for (int i = 0; i < 4; ++i) {
#pragma unroll
        for (int j = 0; j < 4; ++j) {
            wmma::store_matrix_sync(st, acc[i][j], 24, wmma::mem_row_major);
            __syncwarp();
            int row0 = bm + warpRow * 64 + i * 16;
            int col0 = bn + warpCol * 64 + j * 16;
            int r = lane >> 1, c8 = (lane & 1) * 8;
            float4 v0 = *(float4*)&st[r * 24 + c8];
            float4 v1 = *(float4*)&st[r * 24 + c8 + 4];
            const float* bp = bias + col0 + c8;
            v0.x = rtf(v0.x + bp[0]); v0.y = rtf(v0.y + bp[1]);
            v0.z = rtf(v0.z + bp[2]); v0.w = rtf(v0.w + bp[3]);
            v1.x = rtf(v1.x + bp[4]); v1.y = rtf(v1.y + bp[5]);
            v1.z = rtf(v1.z + bp[6]); v1.w = rtf(v1.w + bp[7]);
            float* cp = C + (size_t)(row0 + r) * N + col0 + c8;
            *(float4*)cp = v0;
            *(float4*)(cp + 4) = v1;
            __syncwarp();
        }
    }
}

// ==================== scores (wmma): [64,128]-tile of Q K^T / 8, masked ==============
__global__ void __launch_bounds__(256)
scores_wmma(const float* __restrict__ qh, const float* __restrict__ kv,
            const int* __restrict__ cmask, float* __restrict__ probs) {
    extern __shared__ float sm[];
    float* Qs = sm;            // 64 x ld72
    float* Ks = sm + 4608;     // 128 x ld72
    int bh = blockIdx.y;
    int b = bh >> 4, h = bh & 15;
    int s0 = blockIdx.x * 128;
    int tid = threadIdx.x, wid = tid >> 5, lane = tid & 31;

#pragma unroll
    for (int it = 0; it < 4; ++it) {
        int v = tid + it * 256;
        int r = v >> 4, c = (v & 15) * 4;
        *(float4*)&Qs[r * 72 + c] = *(const float4*)(qh + (size_t)(b * 64 + r) * 1024 + h * 64 + c);
    }
#pragma unroll
    for (int it = 0; it < 8; ++it) {
        int v = tid + it * 256;
        int r = v >> 4, c = (v & 15) * 4;
        *(float4*)&Ks[r * 72 + c] =
            *(const float4*)(kv + (size_t)(b * 2048 + s0 + r) * 2048 + h * 64 + c);
    }
    __syncthreads();

    int warpRow = wid >> 2, warpCol = wid & 3;
    wmma::fragment<wmma::accumulator, 16, 16, 8, float> acc[2][2];
#pragma unroll
    for (int i = 0; i < 2; ++i)
#pragma unroll
        for (int j = 0; j < 2; ++j) wmma::fill_fragment(acc[i][j], 0.0f);

#pragma unroll
    for (int ks = 0; ks < 8; ++ks) {
        int kk = ks * 8;
        wmma::fragment<wmma::matrix_a, 16, 16, 8, wmma::precision::tf32, wmma::row_major> af[2];
        wmma::fragment<wmma::matrix_b, 16, 16, 8, wmma::precision::tf32, wmma::col_major> bf[2];
#pragma unroll
        for (int i = 0; i < 2; ++i)
            wmma::load_matrix_sync(af[i], &Qs[(warpRow * 32 + i * 16) * 72 + kk], 72);
#pragma unroll
        for (int j = 0; j < 2; ++j)
            wmma::load_matrix_sync(bf[j], &Ks[(warpCol * 32 + j * 16) * 72 + kk], 72);
#pragma unroll
        for (int i = 0; i < 2; ++i)
#pragma unroll
            for (int j = 0; j < 2; ++j) wmma::mma_sync(acc[i][j], af[i], bf[j], acc[i][j]);
    }
    __syncthreads();

    const float NEG = __int_as_float(0xff800000);
    float* st = &sm[wid * 384];
#pragma unroll
    for (int i = 0; i < 2; ++i) {
#pragma unroll
        for (int j = 0; j < 2; ++j) {
            wmma::store_matrix_sync(st, acc[i][j], 24, wmma::mem_row_major);
            __syncwarp();
            int r = lane >> 1, c8 = (lane & 1) * 8;
            int l = warpRow * 32 + i * 16 + r;
            int sg = s0 + warpCol * 32 + j * 16 + c8;
            const int* mp = cmask + b * 2048 + sg;
            float4 v0 = *(float4*)&st[r * 24 + c8];
            float4 v1 = *(float4*)&st[r * 24 + c8 + 4];
            v0.x = mp[0] ? v0.x * 0.125f : NEG;
            v0.y = mp[1] ? v0.y * 0.125f : NEG;
            v0.z = mp[2] ? v0.z * 0.125f : NEG;
            v0.w = mp[3] ? v0.w * 0.125f : NEG;
            v1.x = mp[4] ? v1.x * 0.125f : NEG;
            v1.y = mp[5] ? v1.y * 0.125f : NEG;
            v1.z = mp[6] ? v1.z * 0.125f : NEG;
            v1.w = mp[7] ? v1.w * 0.125f : NEG;
            float* pp = probs + ((size_t)bh * 64 + l) * 2048 + sg;
            *(float4*)pp = v0;
            *(float4*)(pp + 4) = v1;
            __syncwarp();
        }
    }
}

// ---------------- row softmax over S=2048, in place; output tf32-rounded ----------
__global__ void softmax_kernel(float* __restrict__ probs) {
    size_t row = blockIdx.x;
    float4* p4 = (float4*)(probs + row * 2048);
    int tid = threadIdx.x;
    float4 x0 = p4[tid], x1 = p4[tid + 256];
    float mx = fmaxf(fmaxf(fmaxf(x0.x, x0.y), fmaxf(x0.z, x0.w)),
                     fmaxf(fmaxf(x1.x, x1.y), fmaxf(x1.z, x1.w)));
    __shared__ float red[256];
    red[tid] = mx;
    __syncthreads();
    for (int st = 128; st > 0; st >>= 1) {
        if (tid < st) red[tid] = fmaxf(red[tid], red[tid + st]);
        __syncthreads();
    }
    float m = red[0];
    __syncthreads();
    float e[8];
    e[0] = expf(x0.x - m); e[1] = expf(x0.y - m); e[2] = expf(x0.z - m); e[3] = expf(x0.w - m);
    e[4] = expf(x1.x - m); e[5] = expf(x1.y - m); e[6] = expf(x1.z - m); e[7] = expf(x1.w - m);
    float s = (e[0] + e[1]) + (e[2] + e[3]) + (e[4] + e[5]) + (e[6] + e[7]);
    red[tid] = s;
    __syncthreads();
    for (int st = 128; st > 0; st >>= 1) {
        if (tid < st) red[tid] += red[tid + st];
        __syncthreads();
    }
    float inv = 1.0f / red[0];
    float4 o0, o1;
    o0.x = rtf(e[0] * inv); o0.y = rtf(e[1] * inv); o0.z = rtf(e[2] * inv); o0.w = rtf(e[3] * inv);
    o1.x = rtf(e[4] * inv); o1.y = rtf(e[5] * inv); o1.z = rtf(e[6] * inv); o1.w = rtf(e[7] * inv);
    p4[tid] = o0;
    p4[tid + 256] = o1;
}

// ==================== attn split-K: partial P @ V ====================
__global__ void __launch_bounds__(256)
attn_part_kernel(const float* __restrict__ probs, const float* __restrict__ kv,
                 float* __restrict__ part) {
    extern __shared__ float sm[];
    int bh = blockIdx.x;
    int b = bh >> 4, h = bh & 15;
    int base_s = blockIdx.y * 512;
    int tid = threadIdx.x, wid = tid >> 5, lane = tid & 31;
    int warpRow = wid >> 1, warpCol = wid & 1;

    uint32_t s_base = (uint32_t)__cvta_generic_to_shared(sm);
    int ra = tid >> 4, ca = (tid & 15) * 4;

    wmma::fragment<wmma::accumulator, 16, 16, 8, float> acc[2];
    wmma::fill_fragment(acc[0], 0.0f);
    wmma::fill_fragment(acc[1], 0.0f);

    auto issue = [&](int stage, int s0) {
        uint32_t ps = s_base + (uint32_t)(stage * 4608) * 4;
        uint32_t vs = s_base + (uint32_t)(9216 + stage * 4608) * 4;
#pragma unroll
        for (int it = 0; it < 4; ++it) {
            int r = ra + it * 16;
            cp16(ps + (uint32_t)(r * 72 + ca) * 4,
                 probs + ((size_t)bh * 64 + r) * 2048 + s0 + ca);
            cp16(vs + (uint32_t)(r * 72 + ca) * 4,
                 kv + (size_t)(b * 2048 + s0 + r) * 2048 + 1024 + h * 64 + ca);
        }
        CP_COMMIT();
    };

    issue(0, base_s);
    for (int kt = 0; kt < 8; ++kt) {
        int stage = kt & 1;
        if (kt + 1 < 8) {
            issue(stage ^ 1, base_s + (kt + 1) * 64);
            CP_WAIT(1);
        } else {
            CP_WAIT(0);
        }
        __syncthreads();
        float* Ps = sm + stage * 4608;
        float* Vs = sm + 9216 + stage * 4608;
#pragma unroll
        for (int ks = 0; ks < 8; ++ks) {
            int kk = ks * 8;
            wmma::fragment<wmma::matrix_a, 16, 16, 8, wmma::precision::tf32, wmma::row_major> af;
            wmma::fragment<wmma::matrix_b, 16, 16, 8, wmma::precision::tf32, wmma::row_major> bf[2];
            wmma::load_matrix_sync(af, &Ps[(warpRow * 16) * 72 + kk], 72);
#pragma unroll
            for (int j = 0; j < 2; ++j)
                wmma::load_matrix_sync(bf[j], &Vs[kk * 72 + warpCol * 32 + j * 16], 72);
            wmma::mma_sync(acc[0], af, bf[0], acc[0]);
            wmma::mma_sync(acc[1], af, bf[1], acc[1]);
        }
        __syncthreads();
    }

    float* pout = part + (size_t)blockIdx.y * 524288;
    float* st = &sm[wid * 384];
#pragma unroll
    for (int j = 0; j < 2; ++j) {
        wmma::store_matrix_sync(st, acc[j], 24, wmma::mem_row_major);
        __syncwarp();
        int r = lane >> 1, c8 = (lane & 1) * 8;
        int l = warpRow * 16 + r;
        int d0 = warpCol * 32 + j * 16 + c8;
        float4 v0 = *(float4*)&st[r * 24 + c8];
        float4 v1 = *(float4*)&st[r * 24 + c8 + 4];
        float* ap = pout + (size_t)(b * 64 + l) * 1024 + h * 64 + d0;
        *(float4*)ap = v0;
        *(float4*)(ap + 4) = v1;
        __syncwarp();
    }
}

// reduce 4 partials -> attn (tf32-rounded)
__global__ void attn_reduce_kernel(const float* __restrict__ part, float* __restrict__ attn) {
    int i = blockIdx.x * 256 + threadIdx.x;
    float4 a = ((const float4*)part)[i];
    float4 b = ((const float4*)(part + 524288))[i];
    float4 c = ((const float4*)(part + 1048576))[i];
    float4 d = ((const float4*)(part + 1572864))[i];
    float4 o;
    o.x = rtf(((a.x + b.x) + (c.x + d.x)));
    o.y = rtf(((a.y + b.y) + (c.y + d.y)));
    o.z = rtf(((a.z + b.z) + (c.z + d.z)));
    o.w = rtf(((a.w + b.w) + (c.w + d.w)));
    ((float4*)attn)[i] = o;
}

// ---------------- residual add + LayerNorm (optional rounded copy) ----------------
template <int WR>
__global__ void add_ln_kernel(const float* __restrict__ a, const float* __restrict__ b2,
                              const float* __restrict__ g, const float* __restrict__ bet,
                              float* __restrict__ out, float* __restrict__ out_r) {
    int row = blockIdx.x, tid = threadIdx.x;
    const float4* a4 = (const float4*)(a + (size_t)row * 1024);
    const float4* b4 = (const float4*)(b2 + (size_t)row * 1024);
    float4 va = a4[tid], vb = b4[tid];
    float4 x;
    x.x = va.x + vb.x; x.y = va.y + vb.y; x.z = va.z + vb.z; x.w = va.w + vb.w;
    float s = (x.x + x.y) + (x.z + x.w);
    float sq = x.x * x.x + x.y * x.y + x.z * x.z + x.w * x.w;
    __shared__ float r1[256], r2[256];
    r1[tid] = s; r2[tid] = sq;
    __syncthreads();
    for (int st = 128; st > 0; st >>= 1) {
        if (tid < st) { r1[tid] += r1[tid + st]; r2[tid] += r2[tid + st]; }
        __syncthreads();
    }
    float mean = r1[0] * (1.0f / 1024.0f);
    float var = r2[0] * (1.0f / 1024.0f) - mean * mean;
    float rstd = rsqrtf(var + 1e-5f);
    float4 gg = ((const float4*)g)[tid], bb = ((const float4*)bet)[tid];
    float4 o;
    o.x = (x.x - mean) * rstd * gg.x + bb.x;
    o.y = (x.y - mean) * rstd * gg.y + bb.y;
    o.z = (x.z - mean) * rstd * gg.z + bb.z;
    o.w = (x.w - mean) * rstd * gg.w + bb.w;
    ((float4*)(out + (size_t)row * 1024))[tid] = o;
    if (WR) {
        float4 q;
        q.x = rtf(o.x); q.y = rtf(o.y); q.z = rtf(o.z); q.w = rtf(o.w);
        ((float4*)(out_r + (size_t)row * 1024))[tid] = q;
    }
}

// ---------------- attn_weights = mean over heads of probs ----------------
__global__ void mean_heads_kernel(const float* __restrict__ probs, float* __restrict__ aw) {
    int i = blockIdx.x * 256 + threadIdx.x;
    int s4 = i & 511;
    int l = (i >> 9) & 63;
    int b = i >> 15;
    float4 acc = {0.f, 0.f, 0.f, 0.f};
#pragma unroll
    for (int h = 0; h < 16; ++h) {
        float4 p = *(const float4*)(probs + ((size_t)(b * 16 + h) * 64 + l) * 2048 + s4 * 4);
        acc.x += p.x; acc.y += p.y; acc.z += p.z; acc.w += p.w;
    }
    const float inv = 1.0f / 16.0f;
    acc.x *= inv; acc.y *= inv; acc.z *= inv; acc.w *= inv;
    *(float4*)(aw + ((size_t)(b * 64 + l) * 2048) + s4 * 4) = acc;
}

// ---------------- launch ----------------
extern "C" void kernel_launch(void* const* d_in, const int* in_sizes, int n_in,
                              void* d_out, int out_size) {
    (void)in_sizes; (void)n_in; (void)out_size;
    const float* latents = (const float*)d_in[0];
    const float* context = (const float*)d_in[1];
    const int* cmask = (const int*)d_in[2];
    const float* q_w = (const float*)d_in[3];
    const float* q_b = (const float*)d_in[4];
    const float* k_w = (const float*)d_in[5];
    const float* k_b = (const float*)d_in[6];
    const float* v_w = (const float*)d_in[7];
    const float* v_b = (const float*)d_in[8];
    const float* in_wq = (const float*)d_in[9];
    const float* in_bq = (const float*)d_in[10];
    const float* in_wk = (const float*)d_in[11];
    const float* in_bk = (const float*)d_in[12];
    const float* in_wv = (const float*)d_in[13];
    const float* in_bv = (const float*)d_in[14];
    const float* out_w = (const float*)d_in[15];
    const float* out_b = (const float*)d_in[16];
    const float* ln1_g = (const float*)d_in[17];
    const float* ln1_b = (const float*)d_in[18];
    const float* ln2_g = (const float*)d_in[19];
    const float* ln2_b = (const float*)d_in[20];
    const float* ff_w1 = (const float*)d_in[21];
    const float* ff_b1 = (const float*)d_in[22];
    const float* ff_w2 = (const float*)d_in[23];
    const float* ff_b2 = (const float*)d_in[24];

    float* out = (float*)d_out;
    float* aw_out = out + 512 * 1024;

    void* p;
    cudaGetSymbolAddress(&p, g_fuse6);  float* fuse6 = (float*)p;
    cudaGetSymbolAddress(&p, g_ctx_r);  float* ctx_r = (float*)p;
    cudaGetSymbolAddress(&p, g_lat_r);  float* lat_r = (float*)p;
    cudaGetSymbolAddress(&p, g_outw_r); float* outw_r = (float*)p;
    cudaGetSymbolAddress(&p, g_ffw1_r); float* ffw1_r = (float*)p;
    cudaGetSymbolAddress(&p, g_ffw2_r); float* ffw2_r = (float*)p;
    cudaGetSymbolAddress(&p, g_Wq);     float* Wq = (float*)p;
    cudaGetSymbolAddress(&p, g_Wkv);    float* Wkv = (float*)p;
    cudaGetSymbolAddress(&p, g_bq);     float* bq = (float*)p;
    cudaGetSymbolAddress(&p, g_bkv);    float* bkv = (float*)p;
    cudaGetSymbolAddress(&p, g_qh);     float* qh = (float*)p;
    cudaGetSymbolAddress(&p, g_kv);     float* kvb = (float*)p;
    cudaGetSymbolAddress(&p, g_probs);  float* probs = (float*)p;
    cudaGetSymbolAddress(&p, g_part);   float* part = (float*)p;
    cudaGetSymbolAddress(&p, g_attn);   float* attn = (float*)p;
    cudaGetSymbolAddress(&p, g_x);      float* xb = (float*)p;
    cudaGetSymbolAddress(&p, g_xr);     float* xr = (float*)p;
    cudaGetSymbolAddress(&p, g_h1);     float* h1 = (float*)p;

    const int SMEM = 81920;
    cudaFuncSetAttribute(wmma_gemm_fuse3, cudaFuncAttributeMaxDynamicSharedMemorySize, SMEM);
    cudaFuncSetAttribute(wmma_gemm_small<0, 1, 1>, cudaFuncAttributeMaxDynamicSharedMemorySize, 61440);
    cudaFuncSetAttribute(wmma_gemm_small<0, 1, 0>, cudaFuncAttributeMaxDynamicSharedMemorySize, 61440);
    cudaFuncSetAttribute(wmma_gemm_small<1, 1, 1>, cudaFuncAttributeMaxDynamicSharedMemorySize, 61440);
    cudaFuncSetAttribute(wmma_gemm_kv, cudaFuncAttributeMaxDynamicSharedMemorySize, 184320);
    cudaFuncSetAttribute(scores_wmma, cudaFuncAttributeMaxDynamicSharedMemorySize, 55296);
    cudaFuncSetAttribute(attn_part_kernel, cudaFuncAttributeMaxDynamicSharedMemorySize, 73728);

    // ---- pre-round operands to tf32 (RNE) ----
    round6_kernel<<<dim3(1024, 6), 256>>>((const float4*)in_wq, (const float4*)q_w,
                                          (const float4*)in_wk, (const float4*)k_w,
                                          (const float4*)in_wv, (const float4*)v_w,
                                          (float4*)fuse6);
    // ctx(4194304) + lat(131072) + outw(262144) + ffw1(1048576) + ffw2(1048576) = 6684672 f4
    round_all_kernel<<<26112, 256>>>((const float4*)context, (float4*)ctx_r, 4194304,
                                     (const float4*)latents, (float4*)lat_r, 131072,
                                     (const float4*)out_w, (float4*)outw_r, 262144,
                                     (const float4*)ff_w1, (float4*)ffw1_r, 1048576,
                                     (const float4*)ff_w2, (float4*)ffw2_r, 1048576);

    // ---- fused weights/biases, batched ----
    fuse_bias_kernel<<<1024, 256>>>(in_wq, q_b, in_bq, bq);
    fuse_bias_kernel<<<1024, 256>>>(in_wk, k_b, in_bk, bkv);
    fuse_bias_kernel<<<1024, 256>>>(in_wv, v_b, in_bv, bkv + 1024);
    const size_t MM = 1024 * 1024;
    wmma_gemm_fuse3<<<dim3(8, 8, 3), 256, SMEM>>>(
        fuse6 + 0 * MM, fuse6 + 1 * MM, Wq,
        fuse6 + 2 * MM, fuse6 + 3 * MM, Wkv,
        fuse6 + 4 * MM, fuse6 + 5 * MM, Wkv + 1024 * 1024);

    // ---- projections ----
    wmma_gemm_small<0, 1, 1><<<dim3(8, 8), 256, 61440>>>(lat_r, Wq, bq, qh, 512, 1024, 1024);
    wmma_gemm_kv<<<dim3(8, 128), 256, 184320>>>(ctx_r, Wkv, bkv, kvb, 16384, 2048, 1024);

    // ---- attention ----
    scores_wmma<<<dim3(16, 128), 256, 55296>>>(qh, kvb, cmask, probs);
    softmax_kernel<<<8192, 256>>>(probs);
    attn_part_kernel<<<dim3(128, 4), 256, 73728>>>(probs, kvb, part);
    attn_reduce_kernel<<<512, 256>>>(part, attn);

    // ---- out projection (reuse qh for attn_out) ----
    wmma_gemm_small<0, 1, 0><<<dim3(8, 8), 256, 61440>>>(attn, outw_r, out_b, qh, 512, 1024, 1024);

    // ---- LN1 (exact + rounded copy) ----
    add_ln_kernel<1><<<512, 256>>>(latents, qh, ln1_g, ln1_b, xb, xr);

    // ---- FFN ----
    wmma_gemm_small<1, 1, 1><<<dim3(32, 8), 256, 61440>>>(xr, ffw1_r, ff_b1, h1, 512, 4096, 1024);
    wmma_gemm_small<0, 1, 0><<<dim3(8, 8), 256, 61440>>>(h1, ffw2_r, ff_b2, attn, 512, 1024, 4096);

    // ---- LN2 -> out ----
    add_ln_kernel<0><<<512, 256>>>(xb, attn, ln2_g, ln2_b, out, nullptr);

    // ---- attn_weights -> second output region ----
    mean_heads_kernel<<<1024, 256>>>(probs, aw_out);
}

// round 9
// speedup vs baseline: 1.1696x; 1.0461x over previous
#include <cuda_runtime.h>
#include <mma.h>
#include <math.h>
#include <stdint.h>

using namespace nvcuda;

// Shapes: B=8, L=64, S=2048, D=1024, C=1024, H=16, HD=64

// ---------------- device scratch ----------------
__device__ float g_fuse6[6 * 1024 * 1024];
__device__ float g_ctx_r[16384 * 1024];
__device__ float g_lat_r[512 * 1024];
__device__ float g_outw_r[1024 * 1024];
__device__ float g_ffw1_r[4096 * 1024];
__device__ float g_ffw2_r[1024 * 4096];
__device__ float g_Wq[1024 * 1024];
__device__ float g_Wkv[2048 * 1024];
__device__ float g_bq[1024];
__device__ float g_bkv[2048];
__device__ float g_qh[512 * 1024];
__device__ float g_kv[16384 * 2048];
__device__ float g_probs[8192 * 2048];
__device__ float g_part[4 * 512 * 1024];
__device__ float g_attn[512 * 1024];
__device__ float g_x[512 * 1024];
__device__ float g_xr[512 * 1024];
__device__ float g_h1[512 * 4096];

__device__ __forceinline__ float gelu_exact(float x) {
    return 0.5f * x * (1.0f + erff(x * 0.70710678118654752f));
}
__device__ __forceinline__ float rtf(float x) {
    float y;
    asm("cvt.rna.tf32.f32 %0, %1;" : "=f"(y) : "f"(x));
    return y;
}
__device__ __forceinline__ void cp16(uint32_t dst, const void* src) {
    asm volatile("cp.async.cg.shared.global [%0], [%1], 16;\n" ::"r"(dst), "l"(src));
}
#define CP_COMMIT() asm volatile("cp.async.commit_group;\n" ::)
#define CP_WAIT(n) asm volatile("cp.async.wait_group %0;\n" ::"n"(n))

// ==================== PROLOGUE: round_all + round6 + fuse_bias (merged) ==============
// blocks [0, 26112): segmented rounding of 5 regions
// blocks [26112, 32256): round6 (z = idx/1024)
// blocks [32256, 35328): fuse_bias (z = idx/1024)
__global__ void prologue_kernel(
    const float4* context, float4* ctx_r,
    const float4* latents4, float4* lat_r,
    const float4* out_w4, float4* outw_r,
    const float4* ff_w14, float4* ffw1_r,
    const float4* ff_w24, float4* ffw2_r,
    const float4* in_wq4, const float4* q_w4, const float4* in_wk4,
    const float4* k_w4, const float4* in_wv4, const float4* v_w4, float4* fuse6,
    const float* in_wq, const float* q_b, const float* in_bq,
    const float* in_wk, const float* k_b, const float* in_bk,
    const float* in_wv, const float* v_b, const float* in_bv,
    float* bq, float* bkv) {
    __shared__ float red[256];
    int bx = blockIdx.x, tid = threadIdx.x;
    if (bx < 26112) {
        int i = bx * 256 + tid;
        const float4* s;
        float4* d;
        int off;
        if (i < 4194304) { s = context; d = ctx_r; off = i; }
        else if ((i -= 4194304) < 131072) { s = latents4; d = lat_r; off = i; }
        else if ((i -= 131072) < 262144) { s = out_w4; d = outw_r; off = i; }
        else if ((i -= 262144) < 1048576) { s = ff_w14; d = ffw1_r; off = i; }
        else { i -= 1048576; s = ff_w24; d = ffw2_r; off = i; }
        float4 v = s[off];
        v.x = rtf(v.x); v.y = rtf(v.y); v.z = rtf(v.z); v.w = rtf(v.w);
        d[off] = v;
    } else if (bx < 32256) {
        int idx = bx - 26112;
        int z = idx >> 10;
        int i = (idx & 1023) * 256 + tid;
        const float4* srcs[6] = {in_wq4, q_w4, in_wk4, k_w4, in_wv4, v_w4};
        float4 v = srcs[z][i];
        v.x = rtf(v.x); v.y = rtf(v.y); v.z = rtf(v.z); v.w = rtf(v.w);
        fuse6[(size_t)z * 262144 + i] = v;
    } else {
        int idx = bx - 32256;
        int z = idx >> 10, o = idx & 1023;
        const float* W = (z == 0) ? in_wq : (z == 1) ? in_wk : in_wv;
        const float* bin = (z == 0) ? q_b : (z == 1) ? k_b : v_b;
        const float* badd = (z == 0) ? in_bq : (z == 1) ? in_bk : in_bv;
        float* bout = (z == 0) ? bq : (z == 1) ? bkv : (bkv + 1024);
        float s = 0.f;
        for (int i = tid; i < 1024; i += 256) s += W[o * 1024 + i] * bin[i];
        red[tid] = s;
        __syncthreads();
        for (int st = 128; st > 0; st >>= 1) {
            if (tid < st) red[tid] += red[tid + st];
            __syncthreads();
        }
        if (tid == 0) bout[o] = red[0] + badd[o];
    }
}

// ==================== TF32 WMMA GEMM 128x128 NN (weight fusion, 2-stage) =============
__device__ __forceinline__ void fuse_body(const float* __restrict__ A, const float* __restrict__ B,
                                          float* __restrict__ C, float* sm) {
    const int N = 1024, K = 1024;
    int tid = threadIdx.x;
    int wid = tid >> 5, lane = tid & 31;
    int warpRow = wid >> 2, warpCol = wid & 3;
    int bm = blockIdx.y * 128, bn = blockIdx.x * 128;

    uint32_t s_base = (uint32_t)__cvta_generic_to_shared(sm);
    int ra = tid >> 3, ca = (tid & 7) * 4;
    int kb = tid >> 5, cb = (tid & 31) * 4;

    wmma::fragment<wmma::accumulator, 16, 16, 8, float> acc[4][2];
#pragma unroll
    for (int i = 0; i < 4; ++i)
#pragma unroll
        for (int j = 0; j < 2; ++j) wmma::fill_fragment(acc[i][j], 0.0f);

    const int KT = K >> 5;
    auto issue = [&](int stage, int k0) {
        uint32_t as = s_base + (uint32_t)(stage * 5120) * 4;
        uint32_t bs = s_base + (uint32_t)(10240 + stage * 5120) * 4;
#pragma unroll
        for (int it = 0; it < 4; ++it) {
            int r = ra + it * 32;
            cp16(as + (uint32_t)(r * 40 + ca) * 4, A + (size_t)(bm + r) * K + k0 + ca);
        }
#pragma unroll
        for (int it = 0; it < 4; ++it) {
            int kk = kb + it * 8;
            cp16(bs + (uint32_t)(kk * 136 + cb) * 4, B + (size_t)(k0 + kk) * N + bn + cb);
        }
        CP_COMMIT();
    };

    issue(0, 0);
    for (int kt = 0; kt < KT; ++kt) {
        int stage = kt & 1;
        if (kt + 1 < KT) {
            issue(stage ^ 1, (kt + 1) * 32);
            CP_WAIT(1);
        } else {
            CP_WAIT(0);
        }
        __syncthreads();
        float* As = sm + stage * 5120;
        float* Bs = sm + 10240 + stage * 5120;
#pragma unroll
        for (int ks = 0; ks < 4; ++ks) {
            int kk = ks * 8;
            wmma::fragment<wmma::matrix_a, 16, 16, 8, wmma::precision::tf32, wmma::row_major> af[4];
#pragma unroll
            for (int i = 0; i < 4; ++i)
                wmma::load_matrix_sync(af[i], &As[(warpRow * 64 + i * 16) * 40 + kk], 40);
            wmma::fragment<wmma::matrix_b, 16, 16, 8, wmma::precision::tf32, wmma::row_major> bf[2];
#pragma unroll
            for (int j = 0; j < 2; ++j)
                wmma::load_matrix_sync(bf[j], &Bs[kk * 136 + warpCol * 32 + j * 16], 136);
#pragma unroll
            for (int i = 0; i < 4; ++i)
#pragma unroll
                for (int j = 0; j < 2; ++j) wmma::mma_sync(acc[i][j], af[i], bf[j], acc[i][j]);
        }
        __syncthreads();
    }

    float* st = &sm[wid * 384];
#pragma unroll
    for (int i = 0; i < 4; ++i) {
#pragma unroll
        for (int j = 0; j < 2; ++j) {
            wmma::store_matrix_sync(st, acc[i][j], 24, wmma::mem_row_major);
            __syncwarp();
            int row0 = bm + warpRow * 64 + i * 16;
            int col0 = bn + warpCol * 32 + j * 16;
            int r = lane >> 1, c8 = (lane & 1) * 8;
            float4 v0 = *(float4*)&st[r * 24 + c8];
            float4 v1 = *(float4*)&st[r * 24 + c8 + 4];
            v0.x = rtf(v0.x); v0.y = rtf(v0.y); v0.z = rtf(v0.z); v0.w = rtf(v0.w);
            v1.x = rtf(v1.x); v1.y = rtf(v1.y); v1.z = rtf(v1.z); v1.w = rtf(v1.w);
            float* cp = C + (size_t)(row0 + r) * N + col0 + c8;
            *(float4*)cp = v0;
            *(float4*)(cp + 4) = v1;
            __syncwarp();
        }
    }
}

__global__ void __launch_bounds__(256, 2)
wmma_gemm_fuse3(const float* A0, const float* B0, float* C0,
                const float* A1, const float* B1, float* C1,
                const float* A2, const float* B2, float* C2) {
    extern __shared__ float sm[];
    if (blockIdx.z == 0) fuse_body(A0, B0, C0, sm);
    else if (blockIdx.z == 1) fuse_body(A1, B1, C1, sm);
    else fuse_body(A2, B2, C2, sm);
}

// ==================== small GEMM body: 64x128 NT, 3-stage, 1 sync/iter ===============
// smem: A stages 3x2560 @0, B stages 3x5120 @7680  => 23040 fl = 92160 B
template <int EPI, int BIAS, int RND>
__device__ __forceinline__ void small_body(const float* __restrict__ A, const float* __restrict__ B,
                                           const float* __restrict__ bias, float* __restrict__ C,
                                           int N, int K, int bm, int bn, float* sm) {
    int tid = threadIdx.x;
    int wid = tid >> 5, lane = tid & 31;
    int warpRow = wid >> 2, warpCol = wid & 3;

    uint32_t s_base = (uint32_t)__cvta_generic_to_shared(sm);
    int ra = tid >> 3, ca = (tid & 7) * 4;

    wmma::fragment<wmma::accumulator, 16, 16, 8, float> acc[2][2];
#pragma unroll
    for (int i = 0; i < 2; ++i)
#pragma unroll
        for (int j = 0; j < 2; ++j) wmma::fill_fragment(acc[i][j], 0.0f);

    const int KT = K >> 5;
    auto issue = [&](int stage, int k0) {
        uint32_t as = s_base + (uint32_t)(stage * 2560) * 4;
        uint32_t bs = s_base + (uint32_t)(7680 + stage * 5120) * 4;
#pragma unroll
        for (int it = 0; it < 2; ++it) {
            int r = ra + it * 32;
            cp16(as + (uint32_t)(r * 40 + ca) * 4, A + (size_t)(bm + r) * K + k0 + ca);
        }
#pragma unroll
        for (int it = 0; it < 4; ++it) {
            int r = ra + it * 32;
            cp16(bs + (uint32_t)(r * 40 + ca) * 4, B + (size_t)(bn + r) * K + k0 + ca);
        }
        CP_COMMIT();
    };

    issue(0, 0);
    if (KT > 1) issue(1, 32);
    for (int kt = 0; kt < KT; ++kt) {
        if (kt + 1 < KT) CP_WAIT(1);
        else CP_WAIT(0);
        __syncthreads();
        if (kt + 2 < KT) issue((kt + 2) % 3, (kt + 2) * 32);
        int stage = kt % 3;
        float* As = sm + stage * 2560;
        float* Bs = sm + 7680 + stage * 5120;
#pragma unroll
        for (int ks = 0; ks < 4; ++ks) {
            int kk = ks * 8;
            wmma::fragment<wmma::matrix_a, 16, 16, 8, wmma::precision::tf32, wmma::row_major> af[2];
            wmma::fragment<wmma::matrix_b, 16, 16, 8, wmma::precision::tf32, wmma::col_major> bf[2];
#pragma unroll
            for (int i = 0; i < 2; ++i)
                wmma::load_matrix_sync(af[i], &As[(warpRow * 32 + i * 16) * 40 + kk], 40);
#pragma unroll
            for (int j = 0; j < 2; ++j)
                wmma::load_matrix_sync(bf[j], &Bs[(warpCol * 32 + j * 16) * 40 + kk], 40);
#pragma unroll
            for (int i = 0; i < 2; ++i)
#pragma unroll
                for (int j = 0; j < 2; ++j) wmma::mma_sync(acc[i][j], af[i], bf[j], acc[i][j]);
        }
    }
    __syncthreads();

    float* st = &sm[wid * 384];
#pragma unroll
    for (int i = 0; i < 2; ++i) {
#pragma unroll
        for (int j = 0; j < 2; ++j) {
            wmma::store_matrix_sync(st, acc[i][j], 24, wmma::mem_row_major);
            __syncwarp();
            int row0 = bm + warpRow * 32 + i * 16;
            int col0 = bn + warpCol * 32 + j * 16;
            int r = lane >> 1, c8 = (lane & 1) * 8;
            float4 v0 = *(float4*)&st[r * 24 + c8];
            float4 v1 = *(float4*)&st[r * 24 + c8 + 4];
            if (BIAS) {
                const float* bp = bias + col0 + c8;
                v0.x += bp[0]; v0.y += bp[1]; v0.z += bp[2]; v0.w += bp[3];
                v1.x += bp[4]; v1.y += bp[5]; v1.z += bp[6]; v1.w += bp[7];
            }
            if (EPI) {
                v0.x = gelu_exact(v0.x); v0.y = gelu_exact(v0.y);
                v0.z = gelu_exact(v0.z); v0.w = gelu_exact(v0.w);
                v1.x = gelu_exact(v1.x); v1.y = gelu_exact(v1.y);
                v1.z = gelu_exact(v1.z); v1.w = gelu_exact(v1.w);
            }
            if (RND) {
                v0.x = rtf(v0.x); v0.y = rtf(v0.y); v0.z = rtf(v0.z); v0.w = rtf(v0.w);
                v1.x = rtf(v1.x); v1.y = rtf(v1.y); v1.z = rtf(v1.z); v1.w = rtf(v1.w);
            }
            float* cp = C + (size_t)(row0 + r) * N + col0 + c8;
            *(float4*)cp = v0;
            *(float4*)(cp + 4) = v1;
            __syncwarp();
        }
    }
}

template <int EPI, int BIAS, int RND>
__global__ void __launch_bounds__(256, 2)
wmma_gemm_small(const float* __restrict__ A, const float* __restrict__ B,
                const float* __restrict__ bias, float* __restrict__ C,
                int M, int N, int K) {
    extern __shared__ float sm[];
    small_body<EPI, BIAS, RND>(A, B, bias, C, N, K, blockIdx.y * 64, blockIdx.x * 128, sm);
}

// ==================== kv GEMM body: 128x256 NT, 3-stage, 1 sync/iter =================
// smem: A stages 3x5120 @0, B stages 3x10240 @15360 => 46080 fl = 184320 B
__device__ __forceinline__ void kv_body(const float* __restrict__ A, const float* __restrict__ B,
                                        const float* __restrict__ bias, float* __restrict__ C,
                                        int bm, int bn, float* sm) {
    const int N = 2048, K = 1024;
    int tid = threadIdx.x;
    int wid = tid >> 5, lane = tid & 31;
    int warpRow = wid >> 2, warpCol = wid & 3;

    uint32_t s_base = (uint32_t)__cvta_generic_to_shared(sm);
    int ra = tid >> 3, ca = (tid & 7) * 4;

    wmma::fragment<wmma::accumulator, 16, 16, 8, float> acc[4][4];
#pragma unroll
    for (int i = 0; i < 4; ++i)
#pragma unroll
        for (int j = 0; j < 4; ++j) wmma::fill_fragment(acc[i][j], 0.0f);

    const int KT = K >> 5;   // 32
    auto issue = [&](int stage, int k0) {
        uint32_t as = s_base + (uint32_t)(stage * 5120) * 4;
        uint32_t bs = s_base + (uint32_t)(15360 + stage * 10240) * 4;
#pragma unroll
        for (int it = 0; it < 4; ++it) {
            int r = ra + it * 32;
            cp16(as + (uint32_t)(r * 40 + ca) * 4, A + (size_t)(bm + r) * K + k0 + ca);
        }
#pragma unroll
        for (int it = 0; it < 8; ++it) {
            int r = ra + it * 32;
            cp16(bs + (uint32_t)(r * 40 + ca) * 4, B + (size_t)(bn + r) * K + k0 + ca);
        }
        CP_COMMIT();
    };

    issue(0, 0);
    issue(1, 32);
    for (int kt = 0; kt < KT; ++kt) {
        if (kt + 1 < KT) CP_WAIT(1);
        else CP_WAIT(0);
        __syncthreads();
        if (kt + 2 < KT) issue((kt + 2) % 3, (kt + 2) * 32);
        int stage = kt % 3;
        float* As = sm + stage * 5120;
        float* Bs = sm + 15360 + stage * 10240;
#pragma unroll
        for (int ks = 0; ks < 4; ++ks) {
            int kk = ks * 8;
            wmma::fragment<wmma::matrix_a, 16, 16, 8, wmma::precision::tf32, wmma::row_major> af[4];
            wmma::fragment<wmma::matrix_b, 16, 16, 8, wmma::precision::tf32, wmma::col_major> bf[4];
#pragma unroll
            for (int i = 0; i < 4; ++i)
                wmma::load_matrix_sync(af[i], &As[(warpRow * 64 + i * 16) * 40 + kk], 40);
#pragma unroll
            for (int j = 0; j < 4; ++j)
                wmma::load_matrix_sync(bf[j], &Bs[(warpCol * 64 + j * 16) * 40 + kk], 40);
#pragma unroll
            for (int i = 0; i < 4; ++i)
#pragma unroll
                for (int j = 0; j < 4; ++j) wmma::mma_sync(acc[i][j], af[i], bf[j], acc[i][j]);
        }
    }
    __syncthreads();

    float* st = &sm[wid * 384];
#pragma unroll
    for (int i = 0; i < 4; ++i) {
#pragma unroll
        for (int j = 0; j < 4; ++j) {
            wmma::store_matrix_sync(st, acc[i][j], 24, wmma::mem_row_major);
            __syncwarp();
            int row0 = bm + warpRow * 64 + i * 16;
            int col0 = bn + warpCol * 64 + j * 16;
            int r = lane >> 1, c8 = (lane & 1) * 8;
            float4 v0 = *(float4*)&st[r * 24 + c8];
            float4 v1 = *(float4*)&st[r * 24 + c8 + 4];
            const float* bp = bias + col0 + c8;
            v0.x = rtf(v0.x + bp[0]); v0.y = rtf(v0.y + bp[1]);
            v0.z = rtf(v0.z + bp[2]); v0.w = rtf(v0.w + bp[3]);
            v1.x = rtf(v1.x + bp[4]); v1.y = rtf(v1.y + bp[5]);
            v1.z = rtf(v1.z + bp[6]); v1.w = rtf(v1.w + bp[7]);
            float* cp = C + (size_t)(row0 + r) * N + col0 + c8;
            *(float4*)cp = v0;
            *(float4*)(cp + 4) = v1;
            __syncwarp();
        }
    }
}

// G1: kv GEMM (blocks 0..1023) + q projection (blocks 1024..1087)
__global__ void __launch_bounds__(256, 1)
g1_kernel(const float* ctx_r, const float* Wkv, const float* bkv, float* kvb,
          const float* lat_r, const float* Wq, const float* bq, float* qh) {
    extern __shared__ float sm[];
    int bx = blockIdx.x;
    if (bx < 1024) {
        kv_body(ctx_r, Wkv, bkv, kvb, (bx >> 3) * 128, (bx & 7) * 256, sm);
    } else {
        int idx = bx - 1024;
        small_body<0, 1, 1>(lat_r, Wq, bq, qh, 1024, 1024, (idx >> 3) * 64, (idx & 7) * 128, sm);
    }
}

// ==================== scores (wmma): [64,128]-tile of Q K^T / 8, masked ==============
__global__ void __launch_bounds__(256)
scores_wmma(const float* __restrict__ qh, const float* __restrict__ kv,
            const int* __restrict__ cmask, float* __restrict__ probs) {
    extern __shared__ float sm[];
    float* Qs = sm;
    float* Ks = sm + 4608;
    int bh = blockIdx.y;
    int b = bh >> 4, h = bh & 15;
    int s0 = blockIdx.x * 128;
    int tid = threadIdx.x, wid = tid >> 5, lane = tid & 31;

#pragma unroll
    for (int it = 0; it < 4; ++it) {
        int v = tid + it * 256;
        int r = v >> 4, c = (v & 15) * 4;
        *(float4*)&Qs[r * 72 + c] = *(const float4*)(qh + (size_t)(b * 64 + r) * 1024 + h * 64 + c);
    }
#pragma unroll
    for (int it = 0; it < 8; ++it) {
        int v = tid + it * 256;
        int r = v >> 4, c = (v & 15) * 4;
        *(float4*)&Ks[r * 72 + c] =
            *(const float4*)(kv + (size_t)(b * 2048 + s0 + r) * 2048 + h * 64 + c);
    }
    __syncthreads();

    int warpRow = wid >> 2, warpCol = wid & 3;
    wmma::fragment<wmma::accumulator, 16, 16, 8, float> acc[2][2];
#pragma unroll
    for (int i = 0; i < 2; ++i)
#pragma unroll
        for (int j = 0; j < 2; ++j) wmma::fill_fragment(acc[i][j], 0.0f);

#pragma unroll
    for (int ks = 0; ks < 8; ++ks) {
        int kk = ks * 8;
        wmma::fragment<wmma::matrix_a, 16, 16, 8, wmma::precision::tf32, wmma::row_major> af[2];
        wmma::fragment<wmma::matrix_b, 16, 16, 8, wmma::precision::tf32, wmma::col_major> bf[2];
#pragma unroll
        for (int i = 0; i < 2; ++i)
            wmma::load_matrix_sync(af[i], &Qs[(warpRow * 32 + i * 16) * 72 + kk], 72);
#pragma unroll
        for (int j = 0; j < 2; ++j)
            wmma::load_matrix_sync(bf[j], &Ks[(warpCol * 32 + j * 16) * 72 + kk], 72);
#pragma unroll
        for (int i = 0; i < 2; ++i)
#pragma unroll
            for (int j = 0; j < 2; ++j) wmma::mma_sync(acc[i][j], af[i], bf[j], acc[i][j]);
    }
    __syncthreads();

    const float NEG = __int_as_float(0xff800000);
    float* st = &sm[wid * 384];
#pragma unroll
    for (int i = 0; i < 2; ++i) {
#pragma unroll
        for (int j = 0; j < 2; ++j) {
            wmma::store_matrix_sync(st, acc[i][j], 24, wmma::mem_row_major);
            __syncwarp();
            int r = lane >> 1, c8 = (lane & 1) * 8;
            int l = warpRow * 32 + i * 16 + r;
            int sg = s0 + warpCol * 32 + j * 16 + c8;
            const int* mp = cmask + b * 2048 + sg;
            float4 v0 = *(float4*)&st[r * 24 + c8];
            float4 v1 = *(float4*)&st[r * 24 + c8 + 4];
            v0.x = mp[0] ? v0.x * 0.125f : NEG;
            v0.y = mp[1] ? v0.y * 0.125f : NEG;
            v0.z = mp[2] ? v0.z * 0.125f : NEG;
            v0.w = mp[3] ? v0.w * 0.125f : NEG;
            v1.x = mp[4] ? v1.x * 0.125f : NEG;
            v1.y = mp[5] ? v1.y * 0.125f : NEG;
            v1.z = mp[6] ? v1.z * 0.125f : NEG;
            v1.w = mp[7] ? v1.w * 0.125f : NEG;
            float* pp = probs + ((size_t)bh * 64 + l) * 2048 + sg;
            *(float4*)pp = v0;
            *(float4*)(pp + 4) = v1;
            __syncwarp();
        }
    }
}

// ---------------- row softmax over S=2048, in place; output tf32-rounded ----------
__global__ void softmax_kernel(float* __restrict__ probs) {
    size_t row = blockIdx.x;
    float4* p4 = (float4*)(probs + row * 2048);
    int tid = threadIdx.x;
    float4 x0 = p4[tid], x1 = p4[tid + 256];
    float mx = fmaxf(fmaxf(fmaxf(x0.x, x0.y), fmaxf(x0.z, x0.w)),
                     fmaxf(fmaxf(x1.x, x1.y), fmaxf(x1.z, x1.w)));
    __shared__ float red[256];
    red[tid] = mx;
    __syncthreads();
    for (int st = 128; st > 0; st >>= 1) {
        if (tid < st) red[tid] = fmaxf(red[tid], red[tid + st]);
        __syncthreads();
    }
    float m = red[0];
    __syncthreads();
    float e[8];
    e[0] = expf(x0.x - m); e[1] = expf(x0.y - m); e[2] = expf(x0.z - m); e[3] = expf(x0.w - m);
    e[4] = expf(x1.x - m); e[5] = expf(x1.y - m); e[6] = expf(x1.z - m); e[7] = expf(x1.w - m);
    float s = (e[0] + e[1]) + (e[2] + e[3]) + (e[4] + e[5]) + (e[6] + e[7]);
    red[tid] = s;
    __syncthreads();
    for (int st = 128; st > 0; st >>= 1) {
        if (tid < st) red[tid] += red[tid + st];
        __syncthreads();
    }
    float inv = 1.0f / red[0];
    float4 o0, o1;
    o0.x = rtf(e[0] * inv); o0.y = rtf(e[1] * inv); o0.z = rtf(e[2] * inv); o0.w = rtf(e[3] * inv);
    o1.x = rtf(e[4] * inv); o1.y = rtf(e[5] * inv); o1.z = rtf(e[6] * inv); o1.w = rtf(e[7] * inv);
    p4[tid] = o0;
    p4[tid + 256] = o1;
}

// ==================== attn split-K body: 3-stage, 1 sync/iter ========================
// smem: Ps stages 3x4608 @0, Vs stages 3x4608 @13824 => 27648 fl = 110592 B
__device__ __forceinline__ void attn_body(const float* __restrict__ probs,
                                          const float* __restrict__ kv,
                                          float* __restrict__ part,
                                          int bh, int split, float* sm) {
    int b = bh >> 4, h = bh & 15;
    int base_s = split * 512;
    int tid = threadIdx.x, wid = tid >> 5, lane = tid & 31;
    int warpRow = wid >> 1, warpCol = wid & 1;

    uint32_t s_base = (uint32_t)__cvta_generic_to_shared(sm);
    int ra = tid >> 4, ca = (tid & 15) * 4;

    wmma::fragment<wmma::accumulator, 16, 16, 8, float> acc[2];
    wmma::fill_fragment(acc[0], 0.0f);
    wmma::fill_fragment(acc[1], 0.0f);

    auto issue = [&](int stage, int s0) {
        uint32_t ps = s_base + (uint32_t)(stage * 4608) * 4;
        uint32_t vs = s_base + (uint32_t)(13824 + stage * 4608) * 4;
#pragma unroll
        for (int it = 0; it < 4; ++it) {
            int r = ra + it * 16;
            cp16(ps + (uint32_t)(r * 72 + ca) * 4,
                 probs + ((size_t)bh * 64 + r) * 2048 + s0 + ca);
            cp16(vs + (uint32_t)(r * 72 + ca) * 4,
                 kv + (size_t)(b * 2048 + s0 + r) * 2048 + 1024 + h * 64 + ca);
        }
        CP_COMMIT();
    };

    issue(0, base_s);
    issue(1, base_s + 64);
    for (int kt = 0; kt < 8; ++kt) {
        if (kt + 1 < 8) CP_WAIT(1);
        else CP_WAIT(0);
        __syncthreads();
        if (kt + 2 < 8) issue((kt + 2) % 3, base_s + (kt + 2) * 64);
        int stage = kt % 3;
        float* Ps = sm + stage * 4608;
        float* Vs = sm + 13824 + stage * 4608;
#pragma unroll
        for (int ks = 0; ks < 8; ++ks) {
            int kk = ks * 8;
            wmma::fragment<wmma::matrix_a, 16, 16, 8, wmma::precision::tf32, wmma::row_major> af;
            wmma::fragment<wmma::matrix_b, 16, 16, 8, wmma::precision::tf32, wmma::row_major> bf[2];
            wmma::load_matrix_sync(af, &Ps[(warpRow * 16) * 72 + kk], 72);
#pragma unroll
            for (int j = 0; j < 2; ++j)
                wmma::load_matrix_sync(bf[j], &Vs[kk * 72 + warpCol * 32 + j * 16], 72);
            wmma::mma_sync(acc[0], af, bf[0], acc[0]);
            wmma::mma_sync(acc[1], af, bf[1], acc[1]);
        }
    }
    __syncthreads();

    float* pout = part + (size_t)split * 524288;
    float* st = &sm[wid * 384];
#pragma unroll
    for (int j = 0; j < 2; ++j) {
        wmma::store_matrix_sync(st, acc[j], 24, wmma::mem_row_major);
        __syncwarp();
        int r = lane >> 1, c8 = (lane & 1) * 8;
        int l = warpRow * 16 + r;
        int d0 = warpCol * 32 + j * 16 + c8;
        float4 v0 = *(float4*)&st[r * 24 + c8];
        float4 v1 = *(float4*)&st[r * 24 + c8 + 4];
        float* ap = pout + (size_t)(b * 64 + l) * 1024 + h * 64 + d0;
        *(float4*)ap = v0;
        *(float4*)(ap + 4) = v1;
        __syncwarp();
    }
}

// A1: attn_part (blocks 0..511) + mean_heads (blocks 512..1535)
__global__ void __launch_bounds__(256, 2)
a1_kernel(const float* __restrict__ probs, const float* __restrict__ kv,
          float* __restrict__ part, float* __restrict__ aw) {
    extern __shared__ float sm[];
    int bx = blockIdx.x;
    if (bx < 512) {
        attn_body(probs, kv, part, bx >> 2, bx & 3, sm);
    } else {
        int i = (bx - 512) * 256 + threadIdx.x;
        int s4 = i & 511;
        int l = (i >> 9) & 63;
        int b = i >> 15;
        float4 acc = {0.f, 0.f, 0.f, 0.f};
#pragma unroll
        for (int h = 0; h < 16; ++h) {
            float4 p = *(const float4*)(probs + ((size_t)(b * 16 + h) * 64 + l) * 2048 + s4 * 4);
            acc.x += p.x; acc.y += p.y; acc.z += p.z; acc.w += p.w;
        }
        const float inv = 1.0f / 16.0f;
        acc.x *= inv; acc.y *= inv; acc.z *= inv; acc.w *= inv;
        *(float4*)(aw + ((size_t)(b * 64 + l) * 2048) + s4 * 4) = acc;
    }
}

// reduce 4 partials -> attn (tf32-rounded)
__global__ void attn_reduce_kernel(const float* __restrict__ part, float* __restrict__ attn) {
    int i = blockIdx.x * 256 + threadIdx.x;
    float4 a = ((const float4*)part)[i];
    float4 b = ((const float4*)(part + 524288))[i];
    float4 c = ((const float4*)(part + 1048576))[i];
    float4 d = ((const float4*)(part + 1572864))[i];
    float4 o;
    o.x = rtf(((a.x + b.x) + (c.x + d.x)));
    o.y = rtf(((a.y + b.y) + (c.y + d.y)));
    o.z = rtf(((a.z + b.z) + (c.z + d.z)));
    o.w = rtf(((a.w + b.w) + (c.w + d.w)));
    ((float4*)attn)[i] = o;
}

// ---------------- residual add + LayerNorm (optional rounded copy) ----------------
template <int WR>
__global__ void add_ln_kernel(const float* __restrict__ a, const float* __restrict__ b2,
                              const float* __restrict__ g, const float* __restrict__ bet,
                              float* __restrict__ out, float* __restrict__ out_r) {
    int row = blockIdx.x, tid = threadIdx.x;
    const float4* a4 = (const float4*)(a + (size_t)row * 1024);
    const float4* b4 = (const float4*)(b2 + (size_t)row * 1024);
    float4 va = a4[tid], vb = b4[tid];
    float4 x;
    x.x = va.x + vb.x; x.y = va.y + vb.y; x.z = va.z + vb.z; x.w = va.w + vb.w;
    float s = (x.x + x.y) + (x.z + x.w);
    float sq = x.x * x.x + x.y * x.y + x.z * x.z + x.w * x.w;
    __shared__ float r1[256], r2[256];
    r1[tid] = s; r2[tid] = sq;
    __syncthreads();
    for (int st = 128; st > 0; st >>= 1) {
        if (tid < st) { r1[tid] += r1[tid + st]; r2[tid] += r2[tid + st]; }
        __syncthreads();
    }
    float mean = r1[0] * (1.0f / 1024.0f);
    float var = r2[0] * (1.0f / 1024.0f) - mean * mean;
    float rstd = rsqrtf(var + 1e-5f);
    float4 gg = ((const float4*)g)[tid], bb = ((const float4*)bet)[tid];
    float4 o;
    o.x = (x.x - mean) * rstd * gg.x + bb.x;
    o.y = (x.y - mean) * rstd * gg.y + bb.y;
    o.z = (x.z - mean) * rstd * gg.z + bb.z;
    o.w = (x.w - mean) * rstd * gg.w + bb.w;
    ((float4*)(out + (size_t)row * 1024))[tid] = o;
    if (WR) {
        float4 q;
        q.x = rtf(o.x); q.y = rtf(o.y); q.z = rtf(o.z); q.w = rtf(o.w);
        ((float4*)(out_r + (size_t)row * 1024))[tid] = q;
    }
}

// ---------------- launch ----------------
extern "C" void kernel_launch(void* const* d_in, const int* in_sizes, int n_in,
                              void* d_out, int out_size) {
    (void)in_sizes; (void)n_in; (void)out_size;
    const float* latents = (const float*)d_in[0];
    const float* context = (const float*)d_in[1];
    const int* cmask = (const int*)d_in[2];
    const float* q_w = (const float*)d_in[3];
    const float* q_b = (const float*)d_in[4];
    const float* k_w = (const float*)d_in[5];
    const float* k_b = (const float*)d_in[6];
    const float* v_w = (const float*)d_in[7];
    const float* v_b = (const float*)d_in[8];
    const float* in_wq = (const float*)d_in[9];
    const float* in_bq = (const float*)d_in[10];
    const float* in_wk = (const float*)d_in[11];
    const float* in_bk = (const float*)d_in[12];
    const float* in_wv = (const float*)d_in[13];
    const float* in_bv = (const float*)d_in[14];
    const float* out_w = (const float*)d_in[15];
    const float* out_b = (const float*)d_in[16];
    const float* ln1_g = (const float*)d_in[17];
    const float* ln1_b = (const float*)d_in[18];
    const float* ln2_g = (const float*)d_in[19];
    const float* ln2_b = (const float*)d_in[20];
    const float* ff_w1 = (const float*)d_in[21];
    const float* ff_b1 = (const float*)d_in[22];
    const float* ff_w2 = (const float*)d_in[23];
    const float* ff_b2 = (const float*)d_in[24];

    float* out = (float*)d_out;
    float* aw_out = out + 512 * 1024;

    void* p;
    cudaGetSymbolAddress(&p, g_fuse6);  float* fuse6 = (float*)p;
    cudaGetSymbolAddress(&p, g_ctx_r);  float* ctx_r = (float*)p;
    cudaGetSymbolAddress(&p, g_lat_r);  float* lat_r = (float*)p;
    cudaGetSymbolAddress(&p, g_outw_r); float* outw_r = (float*)p;
    cudaGetSymbolAddress(&p, g_ffw1_r); float* ffw1_r = (float*)p;
    cudaGetSymbolAddress(&p, g_ffw2_r); float* ffw2_r = (float*)p;
    cudaGetSymbolAddress(&p, g_Wq);     float* Wq = (float*)p;
    cudaGetSymbolAddress(&p, g_Wkv);    float* Wkv = (float*)p;
    cudaGetSymbolAddress(&p, g_bq);     float* bq = (float*)p;
    cudaGetSymbolAddress(&p, g_bkv);    float* bkv = (float*)p;
    cudaGetSymbolAddress(&p, g_qh);     float* qh = (float*)p;
    cudaGetSymbolAddress(&p, g_kv);     float* kvb = (float*)p;
    cudaGetSymbolAddress(&p, g_probs);  float* probs = (float*)p;
    cudaGetSymbolAddress(&p, g_part);   float* part = (float*)p;
    cudaGetSymbolAddress(&p, g_attn);   float* attn = (float*)p;
    cudaGetSymbolAddress(&p, g_x);      float* xb = (float*)p;
    cudaGetSymbolAddress(&p, g_xr);     float* xr = (float*)p;
    cudaGetSymbolAddress(&p, g_h1);     float* h1 = (float*)p;

    cudaFuncSetAttribute(wmma_gemm_fuse3, cudaFuncAttributeMaxDynamicSharedMemorySize, 81920);
    cudaFuncSetAttribute(wmma_gemm_small<0, 1, 0>, cudaFuncAttributeMaxDynamicSharedMemorySize, 92160);
    cudaFuncSetAttribute(wmma_gemm_small<1, 1, 1>, cudaFuncAttributeMaxDynamicSharedMemorySize, 92160);
    cudaFuncSetAttribute(g1_kernel, cudaFuncAttributeMaxDynamicSharedMemorySize, 184320);
    cudaFuncSetAttribute(scores_wmma, cudaFuncAttributeMaxDynamicSharedMemorySize, 55296);
    cudaFuncSetAttribute(a1_kernel, cudaFuncAttributeMaxDynamicSharedMemorySize, 110592);

    // ---- merged prologue: rounding (ctx/lat/outw/ffw1/ffw2 + 6 fusion mats) + biases ----
    prologue_kernel<<<35328, 256>>>(
        (const float4*)context, (float4*)ctx_r,
        (const float4*)latents, (float4*)lat_r,
        (const float4*)out_w, (float4*)outw_r,
        (const float4*)ff_w1, (float4*)ffw1_r,
        (const float4*)ff_w2, (float4*)ffw2_r,
        (const float4*)in_wq, (const float4*)q_w, (const float4*)in_wk,
        (const float4*)k_w, (const float4*)in_wv, (const float4*)v_w, (float4*)fuse6,
        in_wq, q_b, in_bq, in_wk, k_b, in_bk, in_wv, v_b, in_bv, bq, bkv);

    // ---- fused weights (Wq = in_wq@q_w, Wkv = [in_wk@k_w | in_wv@v_w]) ----
    const size_t MM = 1024 * 1024;
    wmma_gemm_fuse3<<<dim3(8, 8, 3), 256, 81920>>>(
        fuse6 + 0 * MM, fuse6 + 1 * MM, Wq,
        fuse6 + 2 * MM, fuse6 + 3 * MM, Wkv,
        fuse6 + 4 * MM, fuse6 + 5 * MM, Wkv + 1024 * 1024);

    // ---- G1: kv projection + q projection (merged) ----
    g1_kernel<<<1088, 256, 184320>>>(ctx_r, Wkv, bkv, kvb, lat_r, Wq, bq, qh);

    // ---- attention ----
    scores_wmma<<<dim3(16, 128), 256, 55296>>>(qh, kvb, cmask, probs);
    softmax_kernel<<<8192, 256>>>(probs);
    a1_kernel<<<1536, 256, 110592>>>(probs, kvb, part, aw_out);
    attn_reduce_kernel<<<512, 256>>>(part, attn);

    // ---- out projection (reuse qh for attn_out) ----
    wmma_gemm_small<0, 1, 0><<<dim3(8, 8), 256, 92160>>>(attn, outw_r, out_b, qh, 512, 1024, 1024);

    // ---- LN1 (exact + rounded copy) ----
    add_ln_kernel<1><<<512, 256>>>(latents, qh, ln1_g, ln1_b, xb, xr);

    // ---- FFN ----
    wmma_gemm_small<1, 1, 1><<<dim3(32, 8), 256, 92160>>>(xr, ffw1_r, ff_b1, h1, 512, 4096, 1024);
    wmma_gemm_small<0, 1, 0><<<dim3(8, 8), 256, 92160>>>(h1, ffw2_r, ff_b2, attn, 512, 1024, 4096);

    // ---- LN2 -> out ----
    add_ln_kernel<0><<<512, 256>>>(xb, attn, ln2_g, ln2_b, out, nullptr);
}

// round 10
// speedup vs baseline: 1.1759x; 1.0054x over previous
#include <cuda_runtime.h>
#include <mma.h>
#include <math.h>
#include <stdint.h>

using namespace nvcuda;

// Shapes: B=8, L=64, S=2048, D=1024, C=1024, H=16, HD=64

// ---------------- device scratch ----------------
__device__ float g_ctx_r[16384 * 1024];
__device__ float g_lat_r[512 * 1024];
__device__ float g_outw_r[1024 * 1024];
__device__ float g_ffw1_r[4096 * 1024];
__device__ float g_ffw2_r[1024 * 4096];
__device__ float g_Wq[1024 * 1024];
__device__ float g_Wkv[2048 * 1024];
__device__ float g_bq[1024];
__device__ float g_bkv[2048];
__device__ float g_qh[512 * 1024];
__device__ float g_kv[16384 * 2048];
__device__ float g_scores[8192 * 2048];     // raw masked/scaled scores
__device__ float g_cstat[8192 * 32];        // per (row, chunk16): (max, sumexp)
__device__ float g_rowstat[8192 * 2];       // per row: (max, 1/sum)
__device__ float g_part[4 * 512 * 1024];
__device__ float g_attn[512 * 1024];
__device__ float g_x[512 * 1024];
__device__ float g_xr[512 * 1024];
__device__ float g_h1[512 * 4096];

__device__ __forceinline__ float gelu_exact(float x) {
    return 0.5f * x * (1.0f + erff(x * 0.70710678118654752f));
}
__device__ __forceinline__ float rtf(float x) {
    float y;
    asm("cvt.rna.tf32.f32 %0, %1;" : "=f"(y) : "f"(x));
    return y;
}
__device__ __forceinline__ void cp16(uint32_t dst, const void* src) {
    asm volatile("cp.async.cg.shared.global [%0], [%1], 16;\n" ::"r"(dst), "l"(src));
}
#define CP_COMMIT() asm volatile("cp.async.commit_group;\n" ::)
#define CP_WAIT(n) asm volatile("cp.async.wait_group %0;\n" ::"n"(n))

// ==================== PROLOGUE: rounding of 5 regions + fuse_bias (merged) ===========
// blocks [0, 26112): segmented rounding; [26112, 29184): fuse_bias
__global__ void prologue_kernel(
    const float4* context, float4* ctx_r,
    const float4* latents4, float4* lat_r,
    const float4* out_w4, float4* outw_r,
    const float4* ff_w14, float4* ffw1_r,
    const float4* ff_w24, float4* ffw2_r,
    const float* in_wq, const float* q_b, const float* in_bq,
    const float* in_wk, const float* k_b, const float* in_bk,
    const float* in_wv, const float* v_b, const float* in_bv,
    float* bq, float* bkv) {
    __shared__ float red[256];
    int bx = blockIdx.x, tid = threadIdx.x;
    if (bx < 26112) {
        int i = bx * 256 + tid;
        const float4* s;
        float4* d;
        int off;
        if (i < 4194304) { s = context; d = ctx_r; off = i; }
        else if ((i -= 4194304) < 131072) { s = latents4; d = lat_r; off = i; }
        else if ((i -= 131072) < 262144) { s = out_w4; d = outw_r; off = i; }
        else if ((i -= 262144) < 1048576) { s = ff_w14; d = ffw1_r; off = i; }
        else { i -= 1048576; s = ff_w24; d = ffw2_r; off = i; }
        float4 v = s[off];
        v.x = rtf(v.x); v.y = rtf(v.y); v.z = rtf(v.z); v.w = rtf(v.w);
        d[off] = v;
    } else {
        int idx = bx - 26112;
        int z = idx >> 10, o = idx & 1023;
        const float* W = (z == 0) ? in_wq : (z == 1) ? in_wk : in_wv;
        const float* bin = (z == 0) ? q_b : (z == 1) ? k_b : v_b;
        const float* badd = (z == 0) ? in_bq : (z == 1) ? in_bk : in_bv;
        float* bout = (z == 0) ? bq : (z == 1) ? bkv : (bkv + 1024);
        float s = 0.f;
        for (int i = tid; i < 1024; i += 256) s += W[o * 1024 + i] * bin[i];
        red[tid] = s;
        __syncthreads();
        for (int st = 128; st > 0; st >>= 1) {
            if (tid < st) red[tid] += red[tid + st];
            __syncthreads();
        }
        if (tid == 0) bout[o] = red[0] + badd[o];
    }
}

// ==================== weight-fusion GEMM 128x128 NN (in-fragment cvt) ================
__device__ __forceinline__ void fuse_body(const float* __restrict__ A, const float* __restrict__ B,
                                          float* __restrict__ C, float* sm) {
    const int N = 1024, K = 1024;
    int tid = threadIdx.x;
    int wid = tid >> 5, lane = tid & 31;
    int warpRow = wid >> 2, warpCol = wid & 3;
    int bm = blockIdx.y * 128, bn = blockIdx.x * 128;

    uint32_t s_base = (uint32_t)__cvta_generic_to_shared(sm);
    int ra = tid >> 3, ca = (tid & 7) * 4;
    int kb = tid >> 5, cb = (tid & 31) * 4;

    wmma::fragment<wmma::accumulator, 16, 16, 8, float> acc[4][2];
#pragma unroll
    for (int i = 0; i < 4; ++i)
#pragma unroll
        for (int j = 0; j < 2; ++j) wmma::fill_fragment(acc[i][j], 0.0f);

    const int KT = K >> 5;
    auto issue = [&](int stage, int k0) {
        uint32_t as = s_base + (uint32_t)(stage * 5120) * 4;
        uint32_t bs = s_base + (uint32_t)(10240 + stage * 5120) * 4;
#pragma unroll
        for (int it = 0; it < 4; ++it) {
            int r = ra + it * 32;
            cp16(as + (uint32_t)(r * 40 + ca) * 4, A + (size_t)(bm + r) * K + k0 + ca);
        }
#pragma unroll
        for (int it = 0; it < 4; ++it) {
            int kk = kb + it * 8;
            cp16(bs + (uint32_t)(kk * 136 + cb) * 4, B + (size_t)(k0 + kk) * N + bn + cb);
        }
        CP_COMMIT();
    };

    issue(0, 0);
    for (int kt = 0; kt < KT; ++kt) {
        int stage = kt & 1;
        if (kt + 1 < KT) {
            issue(stage ^ 1, (kt + 1) * 32);
            CP_WAIT(1);
        } else {
            CP_WAIT(0);
        }
        __syncthreads();
        float* As = sm + stage * 5120;
        float* Bs = sm + 10240 + stage * 5120;
#pragma unroll
        for (int ks = 0; ks < 4; ++ks) {
            int kk = ks * 8;
            wmma::fragment<wmma::matrix_a, 16, 16, 8, wmma::precision::tf32, wmma::row_major> af[4];
#pragma unroll
            for (int i = 0; i < 4; ++i) {
                wmma::load_matrix_sync(af[i], &As[(warpRow * 64 + i * 16) * 40 + kk], 40);
#pragma unroll
                for (int t = 0; t < af[i].num_elements; ++t)
                    af[i].x[t] = wmma::__float_to_tf32(af[i].x[t]);
            }
            wmma::fragment<wmma::matrix_b, 16, 16, 8, wmma::precision::tf32, wmma::row_major> bf[2];
#pragma unroll
            for (int j = 0; j < 2; ++j) {
                wmma::load_matrix_sync(bf[j], &Bs[kk * 136 + warpCol * 32 + j * 16], 136);
#pragma unroll
                for (int t = 0; t < bf[j].num_elements; ++t)
                    bf[j].x[t] = wmma::__float_to_tf32(bf[j].x[t]);
            }
#pragma unroll
            for (int i = 0; i < 4; ++i)
#pragma unroll
                for (int j = 0; j < 2; ++j) wmma::mma_sync(acc[i][j], af[i], bf[j], acc[i][j]);
        }
        __syncthreads();
    }

    float* st = &sm[wid * 384];
#pragma unroll
    for (int i = 0; i < 4; ++i) {
#pragma unroll
        for (int j = 0; j < 2; ++j) {
            wmma::store_matrix_sync(st, acc[i][j], 24, wmma::mem_row_major);
            __syncwarp();
            int row0 = bm + warpRow * 64 + i * 16;
            int col0 = bn + warpCol * 32 + j * 16;
            int r = lane >> 1, c8 = (lane & 1) * 8;
            float4 v0 = *(float4*)&st[r * 24 + c8];
            float4 v1 = *(float4*)&st[r * 24 + c8 + 4];
            v0.x = rtf(v0.x); v0.y = rtf(v0.y); v0.z = rtf(v0.z); v0.w = rtf(v0.w);
            v1.x = rtf(v1.x); v1.y = rtf(v1.y); v1.z = rtf(v1.z); v1.w = rtf(v1.w);
            float* cp = C + (size_t)(row0 + r) * N + col0 + c8;
            *(float4*)cp = v0;
            *(float4*)(cp + 4) = v1;
            __syncwarp();
        }
    }
}

__global__ void __launch_bounds__(256, 2)
wmma_gemm_fuse3(const float* A0, const float* B0, float* C0,
                const float* A1, const float* B1, float* C1,
                const float* A2, const float* B2, float* C2) {
    extern __shared__ float sm[];
    if (blockIdx.z == 0) fuse_body(A0, B0, C0, sm);
    else if (blockIdx.z == 1) fuse_body(A1, B1, C1, sm);
    else fuse_body(A2, B2, C2, sm);
}

// ==================== small GEMM body: 64x128 NT, 3-stage ====================
template <int EPI, int BIAS, int RND>
__device__ __forceinline__ void small_body(const float* __restrict__ A, const float* __restrict__ B,
                                           const float* __restrict__ bias, float* __restrict__ C,
                                           int N, int K, int bm, int bn, float* sm) {
    int tid = threadIdx.x;
    int wid = tid >> 5, lane = tid & 31;
    int warpRow = wid >> 2, warpCol = wid & 3;

    uint32_t s_base = (uint32_t)__cvta_generic_to_shared(sm);
    int ra = tid >> 3, ca = (tid & 7) * 4;

    wmma::fragment<wmma::accumulator, 16, 16, 8, float> acc[2][2];
#pragma unroll
    for (int i = 0; i < 2; ++i)
#pragma unroll
        for (int j = 0; j < 2; ++j) wmma::fill_fragment(acc[i][j], 0.0f);

    const int KT = K >> 5;
    auto issue = [&](int stage, int k0) {
        uint32_t as = s_base + (uint32_t)(stage * 2560) * 4;
        uint32_t bs = s_base + (uint32_t)(7680 + stage * 5120) * 4;
#pragma unroll
        for (int it = 0; it < 2; ++it) {
            int r = ra + it * 32;
            cp16(as + (uint32_t)(r * 40 + ca) * 4, A + (size_t)(bm + r) * K + k0 + ca);
        }
#pragma unroll
        for (int it = 0; it < 4; ++it) {
            int r = ra + it * 32;
            cp16(bs + (uint32_t)(r * 40 + ca) * 4, B + (size_t)(bn + r) * K + k0 + ca);
        }
        CP_COMMIT();
    };

    issue(0, 0);
    if (KT > 1) issue(1, 32);
    for (int kt = 0; kt < KT; ++kt) {
        if (kt + 1 < KT) CP_WAIT(1);
        else CP_WAIT(0);
        __syncthreads();
        if (kt + 2 < KT) issue((kt + 2) % 3, (kt + 2) * 32);
        int stage = kt % 3;
        float* As = sm + stage * 2560;
        float* Bs = sm + 7680 + stage * 5120;
#pragma unroll
        for (int ks = 0; ks < 4; ++ks) {
            int kk = ks * 8;
            wmma::fragment<wmma::matrix_a, 16, 16, 8, wmma::precision::tf32, wmma::row_major> af[2];
            wmma::fragment<wmma::matrix_b, 16, 16, 8, wmma::precision::tf32, wmma::col_major> bf[2];
#pragma unroll
            for (int i = 0; i < 2; ++i)
                wmma::load_matrix_sync(af[i], &As[(warpRow * 32 + i * 16) * 40 + kk], 40);
#pragma unroll
            for (int j = 0; j < 2; ++j)
                wmma::load_matrix_sync(bf[j], &Bs[(warpCol * 32 + j * 16) * 40 + kk], 40);
#pragma unroll
            for (int i = 0; i < 2; ++i)
#pragma unroll
                for (int j = 0; j < 2; ++j) wmma::mma_sync(acc[i][j], af[i], bf[j], acc[i][j]);
        }
    }
    __syncthreads();

    float* st = &sm[wid * 384];
#pragma unroll
    for (int i = 0; i < 2; ++i) {
#pragma unroll
        for (int j = 0; j < 2; ++j) {
            wmma::store_matrix_sync(st, acc[i][j], 24, wmma::mem_row_major);
            __syncwarp();
            int row0 = bm + warpRow * 32 + i * 16;
            int col0 = bn + warpCol * 32 + j * 16;
            int r = lane >> 1, c8 = (lane & 1) * 8;
            float4 v0 = *(float4*)&st[r * 24 + c8];
            float4 v1 = *(float4*)&st[r * 24 + c8 + 4];
            if (BIAS) {
                const float* bp = bias + col0 + c8;
                v0.x += bp[0]; v0.y += bp[1]; v0.z += bp[2]; v0.w += bp[3];
                v1.x += bp[4]; v1.y += bp[5]; v1.z += bp[6]; v1.w += bp[7];
            }
            if (EPI) {
                v0.x = gelu_exact(v0.x); v0.y = gelu_exact(v0.y);
                v0.z = gelu_exact(v0.z); v0.w = gelu_exact(v0.w);
                v1.x = gelu_exact(v1.x); v1.y = gelu_exact(v1.y);
                v1.z = gelu_exact(v1.z); v1.w = gelu_exact(v1.w);
            }
            if (RND) {
                v0.x = rtf(v0.x); v0.y = rtf(v0.y); v0.z = rtf(v0.z); v0.w = rtf(v0.w);
                v1.x = rtf(v1.x); v1.y = rtf(v1.y); v1.z = rtf(v1.z); v1.w = rtf(v1.w);
            }
            float* cp = C + (size_t)(row0 + r) * N + col0 + c8;
            *(float4*)cp = v0;
            *(float4*)(cp + 4) = v1;
            __syncwarp();
        }
    }
}

template <int EPI, int BIAS, int RND>
__global__ void __launch_bounds__(256, 2)
wmma_gemm_small(const float* __restrict__ A, const float* __restrict__ B,
                const float* __restrict__ bias, float* __restrict__ C,
                int M, int N, int K) {
    extern __shared__ float sm[];
    small_body<EPI, BIAS, RND>(A, B, bias, C, N, K, blockIdx.y * 64, blockIdx.x * 128, sm);
}

// ==================== kv GEMM body: 128x256 NT, 3-stage ====================
__device__ __forceinline__ void kv_body(const float* __restrict__ A, const float* __restrict__ B,
                                        const float* __restrict__ bias, float* __restrict__ C,
                                        int bm, int bn, float* sm) {
    const int N = 2048, K = 1024;
    int tid = threadIdx.x;
    int wid = tid >> 5, lane = tid & 31;
    int warpRow = wid >> 2, warpCol = wid & 3;

    uint32_t s_base = (uint32_t)__cvta_generic_to_shared(sm);
    int ra = tid >> 3, ca = (tid & 7) * 4;

    wmma::fragment<wmma::accumulator, 16, 16, 8, float> acc[4][4];
#pragma unroll
    for (int i = 0; i < 4; ++i)
#pragma unroll
        for (int j = 0; j < 4; ++j) wmma::fill_fragment(acc[i][j], 0.0f);

    const int KT = K >> 5;
    auto issue = [&](int stage, int k0) {
        uint32_t as = s_base + (uint32_t)(stage * 5120) * 4;
        uint32_t bs = s_base + (uint32_t)(15360 + stage * 10240) * 4;
#pragma unroll
        for (int it = 0; it < 4; ++it) {
            int r = ra + it * 32;
            cp16(as + (uint32_t)(r * 40 + ca) * 4, A + (size_t)(bm + r) * K + k0 + ca);
        }
#pragma unroll
        for (int it = 0; it < 8; ++it) {
            int r = ra + it * 32;
            cp16(bs + (uint32_t)(r * 40 + ca) * 4, B + (size_t)(bn + r) * K + k0 + ca);
        }
        CP_COMMIT();
    };

    issue(0, 0);
    issue(1, 32);
    for (int kt = 0; kt < KT; ++kt) {
        if (kt + 1 < KT) CP_WAIT(1);
        else CP_WAIT(0);
        __syncthreads();
        if (kt + 2 < KT) issue((kt + 2) % 3, (kt + 2) * 32);
        int stage = kt % 3;
        float* As = sm + stage * 5120;
        float* Bs = sm + 15360 + stage * 10240;
#pragma unroll
        for (int ks = 0; ks < 4; ++ks) {
            int kk = ks * 8;
            wmma::fragment<wmma::matrix_a, 16, 16, 8, wmma::precision::tf32, wmma::row_major> af[4];
            wmma::fragment<wmma::matrix_b, 16, 16, 8, wmma::precision::tf32, wmma::col_major> bf[4];
#pragma unroll
            for (int i = 0; i < 4; ++i)
                wmma::load_matrix_sync(af[i], &As[(warpRow * 64 + i * 16) * 40 + kk], 40);
#pragma unroll
            for (int j = 0; j < 4; ++j)
                wmma::load_matrix_sync(bf[j], &Bs[(warpCol * 64 + j * 16) * 40 + kk], 40);
#pragma unroll
            for (int i = 0; i < 4; ++i)
#pragma unroll
                for (int j = 0; j < 4; ++j) wmma::mma_sync(acc[i][j], af[i], bf[j], acc[i][j]);
        }
    }
    __syncthreads();

    float* st = &sm[wid * 384];
#pragma unroll
    for (int i = 0; i < 4; ++i) {
#pragma unroll
        for (int j = 0; j < 4; ++j) {
            wmma::store_matrix_sync(st, acc[i][j], 24, wmma::mem_row_major);
            __syncwarp();
            int row0 = bm + warpRow * 64 + i * 16;
            int col0 = bn + warpCol * 64 + j * 16;
            int r = lane >> 1, c8 = (lane & 1) * 8;
            float4 v0 = *(float4*)&st[r * 24 + c8];
            float4 v1 = *(float4*)&st[r * 24 + c8 + 4];
            const float* bp = bias + col0 + c8;
            v0.x = rtf(v0.x + bp[0]); v0.y = rtf(v0.y + bp[1]);
            v0.z = rtf(v0.z + bp[2]); v0.w = rtf(v0.w + bp[3]);
            v1.x = rtf(v1.x + bp[4]); v1.y = rtf(v1.y + bp[5]);
            v1.z = rtf(v1.z + bp[6]); v1.w = rtf(v1.w + bp[7]);
            float* cp = C + (size_t)(row0 + r) * N + col0 + c8;
            *(float4*)cp = v0;
            *(float4*)(cp + 4) = v1;
            __syncwarp();
        }
    }
}

// G1: kv GEMM (blocks 0..1023) + q projection (blocks 1024..1087)
__global__ void __launch_bounds__(256, 1)
g1_kernel(const float* ctx_r, const float* Wkv, const float* bkv, float* kvb,
          const float* lat_r, const float* Wq, const float* bq, float* qh) {
    extern __shared__ float sm[];
    int bx = blockIdx.x;
    if (bx < 1024) {
        kv_body(ctx_r, Wkv, bkv, kvb, (bx >> 3) * 128, (bx & 7) * 256, sm);
    } else {
        int idx = bx - 1024;
        small_body<0, 1, 1>(lat_r, Wq, bq, qh, 1024, 1024, (idx >> 3) * 64, (idx & 7) * 128, sm);
    }
}

// ==================== scores: [64,128]-tile of Q K^T / 8, masked + chunk stats =======
// Smem: Qs 64x68 @0, Ks 128x68 @4352 (13056 fl). Staging st @wid*384; pm @3072, ps @3328.
__global__ void __launch_bounds__(256)
scores_wmma(const float* __restrict__ qh, const float* __restrict__ kv,
            const int* __restrict__ cmask, float* __restrict__ scores,
            float* __restrict__ cstat) {
    extern __shared__ float sm[];
    float* Qs = sm;
    float* Ks = sm + 4352;
    int bh = blockIdx.y;
    int b = bh >> 4, h = bh & 15;
    int s0 = blockIdx.x * 128;
    int tid = threadIdx.x, wid = tid >> 5, lane = tid & 31;

#pragma unroll
    for (int it = 0; it < 4; ++it) {
        int v = tid + it * 256;
        int r = v >> 4, c = (v & 15) * 4;
        *(float4*)&Qs[r * 68 + c] = *(const float4*)(qh + (size_t)(b * 64 + r) * 1024 + h * 64 + c);
    }
#pragma unroll
    for (int it = 0; it < 8; ++it) {
        int v = tid + it * 256;
        int r = v >> 4, c = (v & 15) * 4;
        *(float4*)&Ks[r * 68 + c] =
            *(const float4*)(kv + (size_t)(b * 2048 + s0 + r) * 2048 + h * 64 + c);
    }
    __syncthreads();

    int warpRow = wid >> 2, warpCol = wid & 3;
    wmma::fragment<wmma::accumulator, 16, 16, 8, float> acc[2][2];
#pragma unroll
    for (int i = 0; i < 2; ++i)
#pragma unroll
        for (int j = 0; j < 2; ++j) wmma::fill_fragment(acc[i][j], 0.0f);

#pragma unroll
    for (int ks = 0; ks < 8; ++ks) {
        int kk = ks * 8;
        wmma::fragment<wmma::matrix_a, 16, 16, 8, wmma::precision::tf32, wmma::row_major> af[2];
        wmma::fragment<wmma::matrix_b, 16, 16, 8, wmma::precision::tf32, wmma::col_major> bf[2];
#pragma unroll
        for (int i = 0; i < 2; ++i)
            wmma::load_matrix_sync(af[i], &Qs[(warpRow * 32 + i * 16) * 68 + kk], 68);
#pragma unroll
        for (int j = 0; j < 2; ++j)
            wmma::load_matrix_sync(bf[j], &Ks[(warpCol * 32 + j * 16) * 68 + kk], 68);
#pragma unroll
        for (int i = 0; i < 2; ++i)
#pragma unroll
            for (int j = 0; j < 2; ++j) wmma::mma_sync(acc[i][j], af[i], bf[j], acc[i][j]);
    }
    __syncthreads();

    const float NEG = __int_as_float(0xff800000);
    float* st = &sm[wid * 384];
    float* pm = sm + 3072;   // [64][4]
    float* ps = sm + 3328;   // [64][4]
#pragma unroll
    for (int i = 0; i < 2; ++i) {
        int r = lane >> 1, c8 = (lane & 1) * 8;
        int l = warpRow * 32 + i * 16 + r;
        float4 v0, v1, v2, v3;
        wmma::store_matrix_sync(st, acc[i][0], 24, wmma::mem_row_major);
        __syncwarp();
        v0 = *(float4*)&st[r * 24 + c8];
        v1 = *(float4*)&st[r * 24 + c8 + 4];
        __syncwarp();
        wmma::store_matrix_sync(st, acc[i][1], 24, wmma::mem_row_major);
        __syncwarp();
        v2 = *(float4*)&st[r * 24 + c8];
        v3 = *(float4*)&st[r * 24 + c8 + 4];
        __syncwarp();
        int sg0 = s0 + warpCol * 32 + c8;
        int sg1 = sg0 + 16;
        const int* mp0 = cmask + b * 2048 + sg0;
        const int* mp1 = cmask + b * 2048 + sg1;
        v0.x = mp0[0] ? v0.x * 0.125f : NEG;
        v0.y = mp0[1] ? v0.y * 0.125f : NEG;
        v0.z = mp0[2] ? v0.z * 0.125f : NEG;
        v0.w = mp0[3] ? v0.w * 0.125f : NEG;
        v1.x = mp0[4] ? v1.x * 0.125f : NEG;
        v1.y = mp0[5] ? v1.y * 0.125f : NEG;
        v1.z = mp0[6] ? v1.z * 0.125f : NEG;
        v1.w = mp0[7] ? v1.w * 0.125f : NEG;
        v2.x = mp1[0] ? v2.x * 0.125f : NEG;
        v2.y = mp1[1] ? v2.y * 0.125f : NEG;
        v2.z = mp1[2] ? v2.z * 0.125f : NEG;
        v2.w = mp1[3] ? v2.w * 0.125f : NEG;
        v3.x = mp1[4] ? v3.x * 0.125f : NEG;
        v3.y = mp1[5] ? v3.y * 0.125f : NEG;
        v3.z = mp1[6] ? v3.z * 0.125f : NEG;
        v3.w = mp1[7] ? v3.w * 0.125f : NEG;
        float* pp = scores + ((size_t)bh * 64 + l) * 2048 + sg0;
        *(float4*)pp = v0;
        *(float4*)(pp + 4) = v1;
        *(float4*)(pp + 16) = v2;
        *(float4*)(pp + 20) = v3;
        // chunk stats: max + sumexp over this warp's 32 cols of row l
        float mx = fmaxf(fmaxf(fmaxf(v0.x, v0.y), fmaxf(v0.z, v0.w)),
                         fmaxf(fmaxf(v1.x, v1.y), fmaxf(v1.z, v1.w)));
        mx = fmaxf(mx, fmaxf(fmaxf(fmaxf(v2.x, v2.y), fmaxf(v2.z, v2.w)),
                             fmaxf(fmaxf(v3.x, v3.y), fmaxf(v3.z, v3.w))));
        float m2 = fmaxf(mx, __shfl_xor_sync(0xffffffffu, mx, 1));
        float m2c = fmaxf(m2, -1e30f);
        float s = expf(v0.x - m2c) + expf(v0.y - m2c) + expf(v0.z - m2c) + expf(v0.w - m2c) +
                  expf(v1.x - m2c) + expf(v1.y - m2c) + expf(v1.z - m2c) + expf(v1.w - m2c) +
                  expf(v2.x - m2c) + expf(v2.y - m2c) + expf(v2.z - m2c) + expf(v2.w - m2c) +
                  expf(v3.x - m2c) + expf(v3.y - m2c) + expf(v3.z - m2c) + expf(v3.w - m2c);
        s += __shfl_xor_sync(0xffffffffu, s, 1);
        if ((lane & 1) == 0) {
            pm[l * 4 + warpCol] = m2;
            ps[l * 4 + warpCol] = s;
        }
    }
    __syncthreads();
    if (tid < 64) {
        float m0 = pm[tid * 4], m1 = pm[tid * 4 + 1], m2 = pm[tid * 4 + 2], m3 = pm[tid * 4 + 3];
        float m = fmaxf(fmaxf(m0, m1), fmaxf(m2, m3));
        float mc = fmaxf(m, -1e30f);
        float S = ps[tid * 4] * expf(m0 - mc) + ps[tid * 4 + 1] * expf(m1 - mc) +
                  ps[tid * 4 + 2] * expf(m2 - mc) + ps[tid * 4 + 3] * expf(m3 - mc);
        float2 o;
        o.x = m;
        o.y = S;
        *(float2*)&cstat[(((size_t)bh * 64 + tid) * 16 + blockIdx.x) * 2] = o;
    }
}

// ---------------- rowstat: fold 16 chunk stats -> (max, 1/sum) per row ----------------
__global__ void rowstat_kernel(const float* __restrict__ cstat, float* __restrict__ rowstat) {
    int row = blockIdx.x * 256 + threadIdx.x;   // 0..8191
    const float2* c = (const float2*)cstat + row * 16;
    float M = __int_as_float(0xff800000);
#pragma unroll
    for (int k = 0; k < 16; ++k) M = fmaxf(M, c[k].x);
    float Mc = fmaxf(M, -1e30f);
    float S = 0.f;
#pragma unroll
    for (int k = 0; k < 16; ++k) S += c[k].y * expf(c[k].x - Mc);
    float2 o;
    o.x = Mc;
    o.y = 1.0f / S;
    ((float2*)rowstat)[row] = o;
}

// ==================== attn split-K body: inline softmax on staged P tile ==============
// smem: Ps stages 3x4352 @0, Vs stages 3x4352 @13056, rowstats @26112 (m) / 26176 (inv)
__device__ __forceinline__ void attn_body(const float* __restrict__ scores,
                                          const float* __restrict__ kv,
                                          const float* __restrict__ rowstat,
                                          float* __restrict__ part,
                                          int bh, int split, float* sm) {
    int b = bh >> 4, h = bh & 15;
    int base_s = split * 512;
    int tid = threadIdx.x, wid = tid >> 5, lane = tid & 31;
    int warpRow = wid >> 1, warpCol = wid & 1;

    uint32_t s_base = (uint32_t)__cvta_generic_to_shared(sm);
    int ra = tid >> 4, ca = (tid & 15) * 4;
    float* rs_m = sm + 26112;
    float* rs_i = sm + 26176;
    if (tid < 64) {
        float2 v = ((const float2*)rowstat)[bh * 64 + tid];
        rs_m[tid] = v.x;
        rs_i[tid] = v.y;
    }

    wmma::fragment<wmma::accumulator, 16, 16, 8, float> acc[2];
    wmma::fill_fragment(acc[0], 0.0f);
    wmma::fill_fragment(acc[1], 0.0f);

    auto issue = [&](int stage, int s0) {
        uint32_t ps = s_base + (uint32_t)(stage * 4352) * 4;
        uint32_t vs = s_base + (uint32_t)(13056 + stage * 4352) * 4;
#pragma unroll
        for (int it = 0; it < 4; ++it) {
            int r = ra + it * 16;
            cp16(ps + (uint32_t)(r * 68 + ca) * 4,
                 scores + ((size_t)bh * 64 + r) * 2048 + s0 + ca);
            cp16(vs + (uint32_t)(r * 68 + ca) * 4,
                 kv + (size_t)(b * 2048 + s0 + r) * 2048 + 1024 + h * 64 + ca);
        }
        CP_COMMIT();
    };

    issue(0, base_s);
    issue(1, base_s + 64);
    for (int kt = 0; kt < 8; ++kt) {
        if (kt + 1 < 8) CP_WAIT(1);
        else CP_WAIT(0);
        __syncthreads();
        int stage = kt % 3;
        // inline softmax on the P tile this thread loaded
        float* Ps = sm + stage * 4352;
#pragma unroll
        for (int it = 0; it < 4; ++it) {
            int rr = ra + it * 16;
            float M = rs_m[rr], I = rs_i[rr];
            float4 v = *(float4*)&Ps[rr * 68 + ca];
            v.x = rtf(expf(v.x - M) * I);
            v.y = rtf(expf(v.y - M) * I);
            v.z = rtf(expf(v.z - M) * I);
            v.w = rtf(expf(v.w - M) * I);
            *(float4*)&Ps[rr * 68 + ca] = v;
        }
        __syncthreads();
        if (kt + 2 < 8) issue((kt + 2) % 3, base_s + (kt + 2) * 64);
        float* Vs = sm + 13056 + stage * 4352;
#pragma unroll
        for (int ks = 0; ks < 8; ++ks) {
            int kk = ks * 8;
            wmma::fragment<wmma::matrix_a, 16, 16, 8, wmma::precision::tf32, wmma::row_major> af;
            wmma::fragment<wmma::matrix_b, 16, 16, 8, wmma::precision::tf32, wmma::row_major> bf[2];
            wmma::load_matrix_sync(af, &Ps[(warpRow * 16) * 68 + kk], 68);
#pragma unroll
            for (int j = 0; j < 2; ++j)
                wmma::load_matrix_sync(bf[j], &Vs[kk * 68 + warpCol * 32 + j * 16], 68);
            wmma::mma_sync(acc[0], af, bf[0], acc[0]);
            wmma::mma_sync(acc[1], af, bf[1], acc[1]);
        }
    }
    __syncthreads();

    float* pout = part + (size_t)split * 524288;
    float* st = &sm[wid * 384];
#pragma unroll
    for (int j = 0; j < 2; ++j) {
        wmma::store_matrix_sync(st, acc[j], 24, wmma::mem_row_major);
        __syncwarp();
        int r = lane >> 1, c8 = (lane & 1) * 8;
        int l = warpRow * 16 + r;
        int d0 = warpCol * 32 + j * 16 + c8;
        float4 v0 = *(float4*)&st[r * 24 + c8];
        float4 v1 = *(float4*)&st[r * 24 + c8 + 4];
        float* ap = pout + (size_t)(b * 64 + l) * 1024 + h * 64 + d0;
        *(float4*)ap = v0;
        *(float4*)(ap + 4) = v1;
        __syncwarp();
    }
}

// A1: attn_part (blocks 0..511) + mean_heads with inline softmax (blocks 512..1535)
__global__ void __launch_bounds__(256, 2)
a1_kernel(const float* __restrict__ scores, const float* __restrict__ kv,
          const float* __restrict__ rowstat, float* __restrict__ part,
          float* __restrict__ aw) {
    extern __shared__ float sm[];
    int bx = blockIdx.x;
    if (bx < 512) {
        attn_body(scores, kv, rowstat, part, bx >> 2, bx & 3, sm);
    } else {
        int i = (bx - 512) * 256 + threadIdx.x;
        int s4 = i & 511;
        int l = (i >> 9) & 63;
        int b = i >> 15;
        float4 acc = {0.f, 0.f, 0.f, 0.f};
#pragma unroll
        for (int h = 0; h < 16; ++h) {
            size_t row = (size_t)(b * 16 + h) * 64 + l;
            float2 stt = ((const float2*)rowstat)[row];
            float4 x = *(const float4*)(scores + row * 2048 + s4 * 4);
            acc.x += expf(x.x - stt.x) * stt.y;
            acc.y += expf(x.y - stt.x) * stt.y;
            acc.z += expf(x.z - stt.x) * stt.y;
            acc.w += expf(x.w - stt.x) * stt.y;
        }
        const float inv = 1.0f / 16.0f;
        acc.x *= inv; acc.y *= inv; acc.z *= inv; acc.w *= inv;
        *(float4*)(aw + ((size_t)(b * 64 + l) * 2048) + s4 * 4) = acc;
    }
}

// reduce 4 partials -> attn (tf32-rounded)
__global__ void attn_reduce_kernel(const float* __restrict__ part, float* __restrict__ attn) {
    int i = blockIdx.x * 256 + threadIdx.x;
    float4 a = ((const float4*)part)[i];
    float4 b = ((const float4*)(part + 524288))[i];
    float4 c = ((const float4*)(part + 1048576))[i];
    float4 d = ((const float4*)(part + 1572864))[i];
    float4 o;
    o.x = rtf(((a.x + b.x) + (c.x + d.x)));
    o.y = rtf(((a.y + b.y) + (c.y + d.y)));
    o.z = rtf(((a.z + b.z) + (c.z + d.z)));
    o.w = rtf(((a.w + b.w) + (c.w + d.w)));
    ((float4*)attn)[i] = o;
}

// ---------------- residual add + LayerNorm (optional rounded copy) ----------------
template <int WR>
__global__ void add_ln_kernel(const float* __restrict__ a, const float* __restrict__ b2,
                              const float* __restrict__ g, const float* __restrict__ bet,
                              float* __restrict__ out, float* __restrict__ out_r) {
    int row = blockIdx.x, tid = threadIdx.x;
    const float4* a4 = (const float4*)(a + (size_t)row * 1024);
    const float4* b4 = (const float4*)(b2 + (size_t)row * 1024);
    float4 va = a4[tid], vb = b4[tid];
    float4 x;
    x.x = va.x + vb.x; x.y = va.y + vb.y; x.z = va.z + vb.z; x.w = va.w + vb.w;
    float s = (x.x + x.y) + (x.z + x.w);
    float sq = x.x * x.x + x.y * x.y + x.z * x.z + x.w * x.w;
    __shared__ float r1[256], r2[256];
    r1[tid] = s; r2[tid] = sq;
    __syncthreads();
    for (int st = 128; st > 0; st >>= 1) {
        if (tid < st) { r1[tid] += r1[tid + st]; r2[tid] += r2[tid + st]; }
        __syncthreads();
    }
    float mean = r1[0] * (1.0f / 1024.0f);
    float var = r2[0] * (1.0f / 1024.0f) - mean * mean;
    float rstd = rsqrtf(var + 1e-5f);
    float4 gg = ((const float4*)g)[tid], bb = ((const float4*)bet)[tid];
    float4 o;
    o.x = (x.x - mean) * rstd * gg.x + bb.x;
    o.y = (x.y - mean) * rstd * gg.y + bb.y;
    o.z = (x.z - mean) * rstd * gg.z + bb.z;
    o.w = (x.w - mean) * rstd * gg.w + bb.w;
    ((float4*)(out + (size_t)row * 1024))[tid] = o;
    if (WR) {
        float4 q;
        q.x = rtf(o.x); q.y = rtf(o.y); q.z = rtf(o.z); q.w = rtf(o.w);
        ((float4*)(out_r + (size_t)row * 1024))[tid] = q;
    }
}

// ---------------- launch ----------------
extern "C" void kernel_launch(void* const* d_in, const int* in_sizes, int n_in,
                              void* d_out, int out_size) {
    (void)in_sizes; (void)n_in; (void)out_size;
    const float* latents = (const float*)d_in[0];
    const float* context = (const float*)d_in[1];
    const int* cmask = (const int*)d_in[2];
    const float* q_w = (const float*)d_in[3];
    const float* q_b = (const float*)d_in[4];
    const float* k_w = (const float*)d_in[5];
    const float* k_b = (const float*)d_in[6];
    const float* v_w = (const float*)d_in[7];
    const float* v_b = (const float*)d_in[8];
    const float* in_wq = (const float*)d_in[9];
    const float* in_bq = (const float*)d_in[10];
    const float* in_wk = (const float*)d_in[11];
    const float* in_bk = (const float*)d_in[12];
    const float* in_wv = (const float*)d_in[13];
    const float* in_bv = (const float*)d_in[14];
    const float* out_w = (const float*)d_in[15];
    const float* out_b = (const float*)d_in[16];
    const float* ln1_g = (const float*)d_in[17];
    const float* ln1_b = (const float*)d_in[18];
    const float* ln2_g = (const float*)d_in[19];
    const float* ln2_b = (const float*)d_in[20];
    const float* ff_w1 = (const float*)d_in[21];
    const float* ff_b1 = (const float*)d_in[22];
    const float* ff_w2 = (const float*)d_in[23];
    const float* ff_b2 = (const float*)d_in[24];

    float* out = (float*)d_out;
    float* aw_out = out + 512 * 1024;

    void* p;
    cudaGetSymbolAddress(&p, g_ctx_r);   float* ctx_r = (float*)p;
    cudaGetSymbolAddress(&p, g_lat_r);   float* lat_r = (float*)p;
    cudaGetSymbolAddress(&p, g_outw_r);  float* outw_r = (float*)p;
    cudaGetSymbolAddress(&p, g_ffw1_r);  float* ffw1_r = (float*)p;
    cudaGetSymbolAddress(&p, g_ffw2_r);  float* ffw2_r = (float*)p;
    cudaGetSymbolAddress(&p, g_Wq);      float* Wq = (float*)p;
    cudaGetSymbolAddress(&p, g_Wkv);     float* Wkv = (float*)p;
    cudaGetSymbolAddress(&p, g_bq);      float* bq = (float*)p;
    cudaGetSymbolAddress(&p, g_bkv);     float* bkv = (float*)p;
    cudaGetSymbolAddress(&p, g_qh);      float* qh = (float*)p;
    cudaGetSymbolAddress(&p, g_kv);      float* kvb = (float*)p;
    cudaGetSymbolAddress(&p, g_scores);  float* scores = (float*)p;
    cudaGetSymbolAddress(&p, g_cstat);   float* cstat = (float*)p;
    cudaGetSymbolAddress(&p, g_rowstat); float* rowstat = (float*)p;
    cudaGetSymbolAddress(&p, g_part);    float* part = (float*)p;
    cudaGetSymbolAddress(&p, g_attn);    float* attn = (float*)p;
    cudaGetSymbolAddress(&p, g_x);       float* xb = (float*)p;
    cudaGetSymbolAddress(&p, g_xr);      float* xr = (float*)p;
    cudaGetSymbolAddress(&p, g_h1);      float* h1 = (float*)p;

    cudaFuncSetAttribute(wmma_gemm_fuse3, cudaFuncAttributeMaxDynamicSharedMemorySize, 81920);
    cudaFuncSetAttribute(wmma_gemm_small<0, 1, 0>, cudaFuncAttributeMaxDynamicSharedMemorySize, 92160);
    cudaFuncSetAttribute(wmma_gemm_small<1, 1, 1>, cudaFuncAttributeMaxDynamicSharedMemorySize, 92160);
    cudaFuncSetAttribute(g1_kernel, cudaFuncAttributeMaxDynamicSharedMemorySize, 184320);
    cudaFuncSetAttribute(scores_wmma, cudaFuncAttributeMaxDynamicSharedMemorySize, 52224);
    cudaFuncSetAttribute(a1_kernel, cudaFuncAttributeMaxDynamicSharedMemorySize, 104960);

    // ---- merged prologue: rounding (ctx/lat/outw/ffw1/ffw2) + fused biases ----
    prologue_kernel<<<29184, 256>>>(
        (const float4*)context, (float4*)ctx_r,
        (const float4*)latents, (float4*)lat_r,
        (const float4*)out_w, (float4*)outw_r,
        (const float4*)ff_w1, (float4*)ffw1_r,
        (const float4*)ff_w2, (float4*)ffw2_r,
        in_wq, q_b, in_bq, in_wk, k_b, in_bk, in_wv, v_b, in_bv, bq, bkv);

    // ---- fused weights (in-fragment tf32 cvt on raw inputs) ----
    const size_t MM = 1024 * 1024;
    wmma_gemm_fuse3<<<dim3(8, 8, 3), 256, 81920>>>(
        in_wq, q_w, Wq,
        in_wk, k_w, Wkv,
        in_wv, v_w, Wkv + MM);

    // ---- G1: kv projection + q projection (merged) ----
    g1_kernel<<<1088, 256, 184320>>>(ctx_r, Wkv, bkv, kvb, lat_r, Wq, bq, qh);

    // ---- attention: scores(+chunk stats), rowstat fold, split-K P.V w/ inline softmax --
    scores_wmma<<<dim3(16, 128), 256, 52224>>>(qh, kvb, cmask, scores, cstat);
    rowstat_kernel<<<32, 256>>>(cstat, rowstat);
    a1_kernel<<<1536, 256, 104960>>>(scores, kvb, rowstat, part, aw_out);
    attn_reduce_kernel<<<512, 256>>>(part, attn);

    // ---- out projection (reuse qh for attn_out) ----
    wmma_gemm_small<0, 1, 0><<<dim3(8, 8), 256, 92160>>>(attn, outw_r, out_b, qh, 512, 1024, 1024);

    // ---- LN1 (exact + rounded copy) ----
    add_ln_kernel<1><<<512, 256>>>(latents, qh, ln1_g, ln1_b, xb, xr);

    // ---- FFN ----
    wmma_gemm_small<1, 1, 1><<<dim3(32, 8), 256, 92160>>>(xr, ffw1_r, ff_b1, h1, 512, 4096, 1024);
    wmma_gemm_small<0, 1, 0><<<dim3(8, 8), 256, 92160>>>(h1, ffw2_r, ff_b2, attn, 512, 1024, 4096);

    // ---- LN2 -> out ----
    add_ln_kernel<0><<<512, 256>>>(xb, attn, ln2_g, ln2_b, out, nullptr);
}